// round 2
// baseline (speedup 1.0000x reference)
#include <cuda_runtime.h>
#include <math.h>

#define BB 512
#define NN 24
#define TT 25
#define IN_F 8
#define LL 64
#define HH 256
#define OUTF 128
#define XIF 72
#define G4 512

// ---------------- scratch (device globals; allocation-free) ----------------
__device__ float g_xi [BB*NN*XIF];
__device__ float g_h1 [BB*NN*OUTF];
__device__ float g_c1 [BB*NN*OUTF];
__device__ float g_h2 [BB*NN*OUTF];
__device__ float g_c2 [BB*NN*OUTF];
__device__ float g_gts[BB*NN*G4];
__device__ float g_p1 [BB*NN*OUTF];
__device__ float g_p2 [BB*NN*OUTF];
__device__ float g_yi [BB*NN*OUTF];
__device__ float g_yi1[BB*NN*OUTF];
__device__ float g_yi2[BB*NN*OUTF];
__device__ float g_hp [BB*NN*8];
__device__ float g_ls [BB*NN*4];

__device__ __forceinline__ float sigf(float v) { return 1.0f / (1.0f + expf(-v)); }

// ---------------- generic dual-operand tiled fp32 GEMM ----------------
// C[node][row, col] = A1[node][row,:K1] @ W1[node] + A2[node][row,:K2] @ W2[node] + bias[node]
#define BM 128
#define BN 64
#define BKK 8

__device__ __forceinline__ void gemm_tile(
    const float* __restrict__ A, int lda, int K,
    const float* __restrict__ W, int ldw,
    int row0, int col0, int t,
    float (&As)[BKK][BM], float (&Bs)[BKK][BN], float (&acc)[8][4])
{
    const int tx = t & 15, ty = t >> 4;
    for (int k0 = 0; k0 < K; k0 += BKK) {
        // load A tile (transposed into As[k][m]) — 4 floats per thread via float4
        {
            int mm = t >> 1;
            int kk = (t & 1) * 4;
            float4 av = *reinterpret_cast<const float4*>(
                &A[(long)(row0 + mm) * lda + k0 + kk]);
            As[kk + 0][mm] = av.x;
            As[kk + 1][mm] = av.y;
            As[kk + 2][mm] = av.z;
            As[kk + 3][mm] = av.w;
        }
        // load W tile — coalesced
        #pragma unroll
        for (int i = 0; i < 2; i++) {
            int e = t + i * 256;
            int bk = e >> 6, oo = e & 63;
            Bs[bk][oo] = W[(long)(k0 + bk) * ldw + col0 + oo];
        }
        __syncthreads();
        #pragma unroll
        for (int k = 0; k < BKK; k++) {
            float4 a0 = *reinterpret_cast<const float4*>(&As[k][ty * 8]);
            float4 a1 = *reinterpret_cast<const float4*>(&As[k][ty * 8 + 4]);
            float4 bv = *reinterpret_cast<const float4*>(&Bs[k][tx * 4]);
            float a[8] = {a0.x, a0.y, a0.z, a0.w, a1.x, a1.y, a1.z, a1.w};
            float b[4] = {bv.x, bv.y, bv.z, bv.w};
            #pragma unroll
            for (int ii = 0; ii < 8; ii++)
                #pragma unroll
                for (int jj = 0; jj < 4; jj++)
                    acc[ii][jj] += a[ii] * b[jj];
        }
        __syncthreads();
    }
}

__global__ __launch_bounds__(256) void gemm_dual(
    const float* __restrict__ A1, long a1Node, int lda1, int K1,
    const float* __restrict__ A2, long a2Node, int lda2, int K2,
    const float* __restrict__ W1, long w1Node,
    const float* __restrict__ W2, long w2Node,
    const float* __restrict__ bias, long bNode,
    float* __restrict__ C, long cNode, int ldc, int O)
{
    __shared__ float As[BKK][BM];
    __shared__ float Bs[BKK][BN];
    const int node = blockIdx.z;
    const int t = threadIdx.x;
    const int tx = t & 15, ty = t >> 4;
    const int row0 = blockIdx.y * BM;
    const int col0 = blockIdx.x * BN;

    float acc[8][4];
    #pragma unroll
    for (int i = 0; i < 8; i++)
        #pragma unroll
        for (int j = 0; j < 4; j++) acc[i][j] = 0.0f;

    gemm_tile(A1 + (long)node * a1Node, lda1, K1, W1 + (long)node * w1Node, O,
              row0, col0, t, As, Bs, acc);
    if (K2 > 0) {
        gemm_tile(A2 + (long)node * a2Node, lda2, K2, W2 + (long)node * w2Node, O,
                  row0, col0, t, As, Bs, acc);
    }

    const float* bp = bias + (long)node * bNode + col0 + tx * 4;
    float bv0 = bp[0], bv1 = bp[1], bv2 = bp[2], bv3 = bp[3];
    float* cp = C + (long)node * cNode;
    #pragma unroll
    for (int ii = 0; ii < 8; ii++) {
        float4 v = make_float4(acc[ii][0] + bv0, acc[ii][1] + bv1,
                               acc[ii][2] + bv2, acc[ii][3] + bv3);
        *reinterpret_cast<float4*>(
            &cp[(long)(row0 + ty * 8 + ii) * ldc + col0 + tx * 4]) = v;
    }
}

// ---------------- G-mix + LSTM pointwise update ----------------
// grid (m=24, b=512), block 128 (gate channel)
__global__ __launch_bounds__(128) void k_mix_lstm(
    const float* __restrict__ gp, const float* __restrict__ G,
    float* __restrict__ h, float* __restrict__ c, float* __restrict__ yi)
{
    const int m = blockIdx.x, b = blockIdx.y, oc = threadIdx.x;
    __shared__ float Gs[NN];
    if (oc < NN) Gs[oc] = G[m * NN + oc];
    __syncthreads();
    float gi = 0.f, gf = 0.f, gg = 0.f, go = 0.f;
    const float* base = gp + (long)b * NN * G4 + oc;
    #pragma unroll 4
    for (int n = 0; n < NN; n++) {
        float w = Gs[n];
        const float* p = base + n * G4;
        gi += w * p[0];
        gf += w * p[128];
        gg += w * p[256];
        go += w * p[384];
    }
    long idx = ((long)b * NN + m) * OUTF + oc;
    float cc = sigf(gf) * c[idx] + sigf(gi) * tanhf(gg);
    float hh = sigf(go) * tanhf(cc);
    c[idx] = cc;
    h[idx] = hh;
    if (yi) yi[idx] = tanhf(hh);
}

// G-mix + tanh for the two fc branches. grid (24, 512), block 128
__global__ __launch_bounds__(128) void k_mix_tanh2(
    const float* __restrict__ p1, const float* __restrict__ p2,
    const float* __restrict__ G,
    float* __restrict__ o1, float* __restrict__ o2)
{
    const int m = blockIdx.x, b = blockIdx.y, oc = threadIdx.x;
    __shared__ float Gs[NN];
    if (oc < NN) Gs[oc] = G[m * NN + oc];
    __syncthreads();
    float s1 = 0.f, s2 = 0.f;
    long base = (long)b * NN * OUTF + oc;
    #pragma unroll 4
    for (int n = 0; n < NN; n++) {
        float w = Gs[n];
        s1 += w * p1[base + n * OUTF];
        s2 += w * p2[base + n * OUTF];
    }
    long idx = ((long)b * NN + m) * OUTF + oc;
    o1[idx] = tanhf(s1);
    o2[idx] = tanhf(s2);
}

// init: G-mix of the two enc projections -> h0/c0 (duplicated into both LSTMs)
__global__ __launch_bounds__(128) void k_mix_init(
    const float* __restrict__ p1, const float* __restrict__ p2,
    const float* __restrict__ G)
{
    const int m = blockIdx.x, b = blockIdx.y, oc = threadIdx.x;
    __shared__ float Gs[NN];
    if (oc < NN) Gs[oc] = G[m * NN + oc];
    __syncthreads();
    float s1 = 0.f, s2 = 0.f;
    long base = (long)b * NN * OUTF + oc;
    #pragma unroll 4
    for (int n = 0; n < NN; n++) {
        float w = Gs[n];
        s1 += w * p1[base + n * OUTF];
        s2 += w * p2[base + n * OUTF];
    }
    long idx = ((long)b * NN + m) * OUTF + oc;
    g_h1[idx] = s1; g_h2[idx] = s1;
    g_c1[idx] = s2; g_c2[idx] = s2;
}

// ---------------- init xi / loc_start ----------------
__global__ void k_init_xi(const float* __restrict__ x, const float* __restrict__ z)
{
    int idx = blockIdx.x * blockDim.x + threadIdx.x;
    if (idx >= BB * NN * XIF) return;
    int j = idx % XIF;
    int bn = idx / XIF;
    float v;
    if (j < LL) {
        v = z[(long)bn * LL + j];
    } else {
        v = x[(long)bn * IN_F + (j - LL)];
        if (j < LL + 4) g_ls[(long)bn * 4 + (j - LL)] = v;
    }
    g_xi[idx] = v;
}

// ---------------- per-(b,n) head pre-projection: [3 loc | 4 logz] ----------------
// one warp per (b,n); grid = 12288/4 blocks of 128
__global__ __launch_bounds__(128) void k_head_pre(
    const float* __restrict__ locW, const float* __restrict__ logzW)
{
    int w = blockIdx.x * 4 + (threadIdx.x >> 5);
    int lane = threadIdx.x & 31;
    long base = (long)w * OUTF + lane * 4;
    float4 v1 = *reinterpret_cast<const float4*>(&g_yi1[base]);
    float4 v2 = *reinterpret_cast<const float4*>(&g_yi2[base]);
    float a[7] = {0.f, 0.f, 0.f, 0.f, 0.f, 0.f, 0.f};
    float x1[4] = {v1.x, v1.y, v1.z, v1.w};
    float x2[4] = {v2.x, v2.y, v2.z, v2.w};
    #pragma unroll
    for (int j = 0; j < 4; j++) {
        int f = lane * 4 + j;
        a[0] += x1[j] * locW[f * 3 + 0];
        a[1] += x1[j] * locW[f * 3 + 1];
        a[2] += x1[j] * locW[f * 3 + 2];
        a[3] += x2[j] * logzW[f * 4 + 0];
        a[4] += x2[j] * logzW[f * 4 + 1];
        a[5] += x2[j] * logzW[f * 4 + 2];
        a[6] += x2[j] * logzW[f * 4 + 3];
    }
    #pragma unroll
    for (int s = 16; s > 0; s >>= 1)
        #pragma unroll
        for (int k = 0; k < 7; k++)
            a[k] += __shfl_xor_sync(0xFFFFFFFFu, a[k], s);
    if (lane == 0) {
        #pragma unroll
        for (int k = 0; k < 7; k++) g_hp[(long)w * 8 + k] = a[k];
    }
}

// ---------------- final: G-mix head, normalize, quat-mul, outputs, next xi ----------------
// grid = 512 (b), block 64
__global__ __launch_bounds__(64) void k_final(
    const float* __restrict__ G,
    const float* __restrict__ locb, const float* __restrict__ logzb,
    float* __restrict__ out, int t)
{
    const int b = blockIdx.x;
    const int tid = threadIdx.x;
    __shared__ float hps[NN][8];
    for (int e = tid; e < NN * 8; e += 64)
        (&hps[0][0])[e] = g_hp[(long)b * NN * 8 + e];
    __syncthreads();
    if (tid < NN) {
        const int m = tid;
        float l0 = locb[0], l1 = locb[1], l2 = locb[2];
        float z0 = logzb[0], z1 = logzb[1], z2 = logzb[2], z3 = logzb[3];
        #pragma unroll 4
        for (int n = 0; n < NN; n++) {
            float w = G[m * NN + n];
            l0 += w * hps[n][0]; l1 += w * hps[n][1]; l2 += w * hps[n][2];
            z0 += w * hps[n][3]; z1 += w * hps[n][4];
            z2 += w * hps[n][5]; z3 += w * hps[n][6];
        }
        float r = rsqrtf(1.0f + l0 * l0 + l1 * l1 + l2 * l2);
        float d0 = r, d1 = l0 * r, d2 = l1 * r, d3 = l2 * r;
        float* ls = &g_ls[((long)b * NN + m) * 4];
        float w1 = ls[0], x1 = ls[1], y1 = ls[2], zz1 = ls[3];
        float q0 = w1 * d0 - x1 * d1 - y1 * d2 - zz1 * d3;
        float q1 = w1 * d1 + x1 * d0 + y1 * d3 - zz1 * d2;
        float q2 = w1 * d2 - x1 * d3 + y1 * d0 + zz1 * d1;
        float q3 = w1 * d3 + x1 * d2 - y1 * d1 + zz1 * d0;
        ls[0] = q0; ls[1] = q1; ls[2] = q2; ls[3] = q3;
        long ob = (((long)b * TT + t) * NN + m) * 4;
        out[ob + 0] = q0; out[ob + 1] = q1; out[ob + 2] = q2; out[ob + 3] = q3;
        const long ZOFF = (long)BB * TT * NN * 4;
        out[ZOFF + ob + 0] = z0; out[ZOFF + ob + 1] = z1;
        out[ZOFF + ob + 2] = z2; out[ZOFF + ob + 3] = z3;
        float* xr = &g_xi[((long)b * NN + m) * XIF];
        xr[64] = q0; xr[65] = q1; xr[66] = q2; xr[67] = q3;
        xr[68] = d0; xr[69] = d1; xr[70] = d2; xr[71] = d3;
    }
}

// ---------------- host ----------------
extern "C" void kernel_launch(void* const* d_in, const int* in_sizes, int n_in,
                              void* d_out, int out_size)
{
    const float* x     = (const float*)d_in[0];
    const float* enc   = (const float*)d_in[1];
    const float* z     = (const float*)d_in[2];
    /* d_in[3] = y, unused by the reference */
    const float* G     = (const float*)d_in[4];
    const float* Wx0   = (const float*)d_in[5];
    const float* Wh0   = (const float*)d_in[6];
    const float* b0    = (const float*)d_in[7];
    const float* Wx1   = (const float*)d_in[8];
    const float* Wh1   = (const float*)d_in[9];
    const float* b1    = (const float*)d_in[10];
    const float* fcW   = (const float*)d_in[11];
    const float* fcb   = (const float*)d_in[12];
    const float* fc2W  = (const float*)d_in[13];
    const float* fc2b  = (const float*)d_in[14];
    const float* ih1W  = (const float*)d_in[15];
    const float* ih1b  = (const float*)d_in[16];
    const float* ih2W  = (const float*)d_in[17];
    const float* ih2b  = (const float*)d_in[18];
    const float* locW  = (const float*)d_in[19];
    const float* locb  = (const float*)d_in[20];
    const float* logzW = (const float*)d_in[21];
    const float* logzb = (const float*)d_in[22];
    float* out = (float*)d_out;

    float *xi, *h1, *c1, *h2, *c2, *gts, *p1, *p2, *yi, *yi1, *yi2;
    cudaGetSymbolAddress((void**)&xi,  g_xi);
    cudaGetSymbolAddress((void**)&h1,  g_h1);
    cudaGetSymbolAddress((void**)&c1,  g_c1);
    cudaGetSymbolAddress((void**)&h2,  g_h2);
    cudaGetSymbolAddress((void**)&c2,  g_c2);
    cudaGetSymbolAddress((void**)&gts, g_gts);
    cudaGetSymbolAddress((void**)&p1,  g_p1);
    cudaGetSymbolAddress((void**)&p2,  g_p2);
    cudaGetSymbolAddress((void**)&yi,  g_yi);
    cudaGetSymbolAddress((void**)&yi1, g_yi1);
    cudaGetSymbolAddress((void**)&yi2, g_yi2);

    // ---- init ----
    {
        int tot = BB * NN * XIF;
        k_init_xi<<<(tot + 255) / 256, 256>>>(x, z);
    }
    // enc @ ih1_W -> p1 ; enc @ ih2_W -> p2  (rows = B*N = 12288, shared weights)
    {
        dim3 grid(OUTF / BN, (BB * NN) / BM, 1);
        gemm_dual<<<grid, 256>>>(enc, 0, HH, HH,
                                 enc, 0, HH, 0,
                                 ih1W, 0, ih1W, 0,
                                 ih1b, 0,
                                 p1, 0, OUTF, OUTF);
        gemm_dual<<<grid, 256>>>(enc, 0, HH, HH,
                                 enc, 0, HH, 0,
                                 ih2W, 0, ih2W, 0,
                                 ih2b, 0,
                                 p2, 0, OUTF, OUTF);
    }
    {
        dim3 grid(NN, BB);
        k_mix_init<<<grid, 128>>>(p1, p2, G);
    }

    // ---- T sequential steps ----
    for (int t = 0; t < TT; t++) {
        // LSTM1 gates: xi @ Wx0[n] + h1 @ Wh0[n] + b0[n]
        {
            dim3 grid(G4 / BN, BB / BM, NN);
            gemm_dual<<<grid, 256>>>(xi, XIF, NN * XIF, XIF,
                                     h1, OUTF, NN * OUTF, OUTF,
                                     Wx0, (long)XIF * G4,
                                     Wh0, (long)OUTF * G4,
                                     b0, G4,
                                     gts, G4, NN * G4, G4);
        }
        { dim3 grid(NN, BB); k_mix_lstm<<<grid, 128>>>(gts, G, h1, c1, nullptr); }
        // LSTM2 gates: h1 @ Wx1[n] + h2 @ Wh1[n] + b1[n]
        {
            dim3 grid(G4 / BN, BB / BM, NN);
            gemm_dual<<<grid, 256>>>(h1, OUTF, NN * OUTF, OUTF,
                                     h2, OUTF, NN * OUTF, OUTF,
                                     Wx1, (long)OUTF * G4,
                                     Wh1, (long)OUTF * G4,
                                     b1, G4,
                                     gts, G4, NN * G4, G4);
        }
        { dim3 grid(NN, BB); k_mix_lstm<<<grid, 128>>>(gts, G, h2, c2, yi); }
        // fc / fc2: yi @ fc_W[n] + fc_b[n]
        {
            dim3 grid(OUTF / BN, BB / BM, NN);
            gemm_dual<<<grid, 256>>>(yi, OUTF, NN * OUTF, OUTF,
                                     yi, OUTF, NN * OUTF, 0,
                                     fcW, (long)OUTF * OUTF,
                                     fcW, 0,
                                     fcb, OUTF,
                                     p1, OUTF, NN * OUTF, OUTF);
            gemm_dual<<<grid, 256>>>(yi, OUTF, NN * OUTF, OUTF,
                                     yi, OUTF, NN * OUTF, 0,
                                     fc2W, (long)OUTF * OUTF,
                                     fc2W, 0,
                                     fc2b, OUTF,
                                     p2, OUTF, NN * OUTF, OUTF);
        }
        { dim3 grid(NN, BB); k_mix_tanh2<<<grid, 128>>>(p1, p2, G, yi1, yi2); }
        // head projections + finalize
        k_head_pre<<<(BB * NN) / 4, 128>>>(locW, logzW);
        k_final<<<BB, 64>>>(G, locb, logzb, out, t);
    }
}

// round 3
// speedup vs baseline: 1.8308x; 1.8308x over previous
#include <cuda_runtime.h>
#include <math.h>

#define BB 512
#define NN 24
#define TT 25
#define IN_F 8
#define LL 64
#define HH 256
#define OUTF 128
#define XIF 72
#define G4 512

typedef unsigned long long ull;

// ---------------- scratch (device globals; allocation-free) ----------------
__device__ float g_xi [BB*NN*XIF];
__device__ float g_h1 [BB*NN*OUTF];
__device__ float g_c1 [BB*NN*OUTF];
__device__ float g_h2 [BB*NN*OUTF];
__device__ float g_c2 [BB*NN*OUTF];
__device__ float g_gts[BB*NN*G4];
__device__ float g_p1 [BB*NN*OUTF];
__device__ float g_p2 [BB*NN*OUTF];
__device__ float g_yi [BB*NN*OUTF];
__device__ float g_yi1[BB*NN*OUTF];
__device__ float g_yi2[BB*NN*OUTF];
__device__ float g_hp [BB*NN*8];
__device__ float g_ls [BB*NN*4];

__device__ __forceinline__ float sigf(float v) { return 1.0f / (1.0f + expf(-v)); }

// ---------------- packed f32x2 helpers (full-rate fp32 on sm_103a) ----------------
__device__ __forceinline__ ull fma2(ull a, ull b, ull c) {
    ull d; asm("fma.rn.f32x2 %0, %1, %2, %3;" : "=l"(d) : "l"(a), "l"(b), "l"(c));
    return d;
}
__device__ __forceinline__ ull dup2(float x) {
    ull d; asm("mov.b64 %0, {%1, %1};" : "=l"(d) : "f"(x)); return d;
}
__device__ __forceinline__ ull pk2(float x, float y) {
    ull d; asm("mov.b64 %0, {%1, %2};" : "=l"(d) : "f"(x), "f"(y)); return d;
}
__device__ __forceinline__ float2 upk2(ull v) {
    float2 r; asm("mov.b64 {%0, %1}, %2;" : "=f"(r.x), "=f"(r.y) : "l"(v)); return r;
}

// ---------------- 128x128 dual-operand fp32 GEMM, f32x2 core ----------------
#define BMX 128
#define BNX 128
#define APAD 132

__device__ __forceinline__ void gphase(
    const float* __restrict__ A, int lda, int K,
    const float* __restrict__ W, int ldw, int col0,
    int row0, int t, float* As, float* Bs, ull* acc)
{
    const int arow = t >> 1, akk = (t & 1) * 4;
    const int brow = t >> 5, bcol = (t & 31) * 4;
    const int tx = t & 15, ty = t >> 4;
    const int nt = K >> 3;
    const float* aptr = A + (long)(row0 + arow) * lda + akk;
    const float* bptr = W + (long)brow * ldw + col0 + bcol;
    float4 pa = *(const float4*)aptr;
    float4 pb = *(const float4*)bptr;
    for (int it = 0; it < nt; it++) {
        float* as = As + (it & 1) * (8 * APAD);
        float* bs = Bs + (it & 1) * (8 * 128);
        as[(akk + 0) * APAD + arow] = pa.x;
        as[(akk + 1) * APAD + arow] = pa.y;
        as[(akk + 2) * APAD + arow] = pa.z;
        as[(akk + 3) * APAD + arow] = pa.w;
        *(float4*)&bs[brow * 128 + bcol] = pb;
        __syncthreads();
        if (it + 1 < nt) {
            pa = *(const float4*)(aptr + (it + 1) * 8);
            pb = *(const float4*)(bptr + (long)(it + 1) * 8 * ldw);
        }
        #pragma unroll
        for (int k = 0; k < 8; k++) {
            float4 a0 = *(const float4*)&as[k * APAD + ty * 8];
            float4 a1 = *(const float4*)&as[k * APAD + ty * 8 + 4];
            float4 b0 = *(const float4*)&bs[k * 128 + tx * 8];
            float4 b1 = *(const float4*)&bs[k * 128 + tx * 8 + 4];
            ull bb[4] = { pk2(b0.x, b0.y), pk2(b0.z, b0.w),
                          pk2(b1.x, b1.y), pk2(b1.z, b1.w) };
            float av[8] = {a0.x, a0.y, a0.z, a0.w, a1.x, a1.y, a1.z, a1.w};
            #pragma unroll
            for (int i = 0; i < 8; i++) {
                ull ad = dup2(av[i]);
                #pragma unroll
                for (int j = 0; j < 4; j++)
                    acc[i * 4 + j] = fma2(ad, bb[j], acc[i * 4 + j]);
            }
        }
    }
    __syncthreads();
}

// C[node] = A1[node] @ W1[node] (+ A2[node] @ W2[node]) + bias[node]
// blocks with blockIdx.z >= nodes use the "alt" weight/bias/output set.
__global__ __launch_bounds__(256, 2) void gemm128(
    const float* __restrict__ A1, long a1n, int lda1, int K1,
    const float* __restrict__ A2, long a2n, int lda2, int K2,
    const float* __restrict__ W1, const float* __restrict__ W1b, long w1n,
    const float* __restrict__ W2, long w2n,
    const float* __restrict__ bias, const float* __restrict__ biasb, long bn,
    float* __restrict__ C, float* __restrict__ Cb, long cn, int ldc, int O, int nodes)
{
    __shared__ float As[2 * 8 * APAD];
    __shared__ float Bs[2 * 8 * 128];
    int z = blockIdx.z, node = z;
    const float* w1 = W1; const float* bsrc = bias; float* c = C;
    if (z >= nodes) { node = z - nodes; w1 = W1b; bsrc = biasb; c = Cb; }
    const int t = threadIdx.x;
    const int tx = t & 15, ty = t >> 4;
    const int row0 = blockIdx.y * BMX;
    const int col0 = blockIdx.x * BNX;

    ull acc[32];
    #pragma unroll
    for (int i = 0; i < 32; i++) acc[i] = 0ull;

    gphase(A1 + (long)node * a1n, lda1, K1, w1 + (long)node * w1n, O, col0,
           row0, t, As, Bs, acc);
    if (K2 > 0)
        gphase(A2 + (long)node * a2n, lda2, K2, W2 + (long)node * w2n, O, col0,
               row0, t, As, Bs, acc);

    const float* bp = bsrc + (long)node * bn + col0 + tx * 8;
    float4 bv0 = *(const float4*)bp;
    float4 bv1 = *(const float4*)(bp + 4);
    float* cbase = c + (long)node * cn;
    #pragma unroll
    for (int i = 0; i < 8; i++) {
        float2 v0 = upk2(acc[i * 4 + 0]);
        float2 v1 = upk2(acc[i * 4 + 1]);
        float2 v2 = upk2(acc[i * 4 + 2]);
        float2 v3 = upk2(acc[i * 4 + 3]);
        float4 o0 = make_float4(v0.x + bv0.x, v0.y + bv0.y, v1.x + bv0.z, v1.y + bv0.w);
        float4 o1 = make_float4(v2.x + bv1.x, v2.y + bv1.y, v3.x + bv1.z, v3.y + bv1.w);
        float* cp = cbase + (long)(row0 + ty * 8 + i) * ldc + col0 + tx * 8;
        *(float4*)cp = o0;
        *(float4*)(cp + 4) = o1;
    }
}

// ---------------- fast G-mix + LSTM pointwise ----------------
// grid (2, 512): blockIdx.x = oc-half (64 ch), blockIdx.y = b. 256 threads.
__global__ __launch_bounds__(256) void k_mix_lstm_f(
    const float* __restrict__ gp, const float* __restrict__ G,
    float* __restrict__ h, float* __restrict__ c, float* __restrict__ yi)
{
    __shared__ float sg[NN * 256];   // [n][gate*64 + ocl]
    __shared__ float sG[NN * NN];
    const int och = blockIdx.x, b = blockIdx.y;
    const int t = threadIdx.x;
    const float* src = gp + (long)b * NN * G4;
    for (int e4 = t; e4 < NN * 256 / 4; e4 += 256) {
        int e = e4 * 4;
        int n = e >> 8, col = e & 255, g = col >> 6, j = col & 63;
        *(float4*)&sg[e] = *(const float4*)&src[n * G4 + g * 128 + och * 64 + j];
    }
    for (int e = t; e < NN * NN; e += 256) sG[e] = G[e];
    __syncthreads();

    const int ocl = t & 63;
    const int m0 = (t >> 6) * 6;
    float acc[6][4];
    #pragma unroll
    for (int j = 0; j < 6; j++)
        #pragma unroll
        for (int g = 0; g < 4; g++) acc[j][g] = 0.f;
    for (int n = 0; n < NN; n++) {
        float gv0 = sg[n * 256 + ocl];
        float gv1 = sg[n * 256 + 64 + ocl];
        float gv2 = sg[n * 256 + 128 + ocl];
        float gv3 = sg[n * 256 + 192 + ocl];
        #pragma unroll
        for (int j = 0; j < 6; j++) {
            float w = sG[(m0 + j) * NN + n];
            acc[j][0] += w * gv0; acc[j][1] += w * gv1;
            acc[j][2] += w * gv2; acc[j][3] += w * gv3;
        }
    }
    const int oc = och * 64 + ocl;
    #pragma unroll
    for (int j = 0; j < 6; j++) {
        long idx = ((long)b * NN + m0 + j) * OUTF + oc;
        float cc = sigf(acc[j][1]) * c[idx] + sigf(acc[j][0]) * tanhf(acc[j][2]);
        float hh = sigf(acc[j][3]) * tanhf(cc);
        c[idx] = cc;
        h[idx] = hh;
        if (yi) yi[idx] = tanhf(hh);
    }
}

// ---------------- fast G-mix + tanh for fc branches ----------------
// grid (512): one block per b. 256 threads.
__global__ __launch_bounds__(256) void k_mix_tanh2_f(
    const float* __restrict__ p1, const float* __restrict__ p2,
    const float* __restrict__ G,
    float* __restrict__ o1, float* __restrict__ o2)
{
    __shared__ float s1[NN * OUTF];
    __shared__ float s2[NN * OUTF];
    __shared__ float sG[NN * NN];
    const int b = blockIdx.x;
    const int t = threadIdx.x;
    const float* q1 = p1 + (long)b * NN * OUTF;
    const float* q2 = p2 + (long)b * NN * OUTF;
    for (int e4 = t; e4 < NN * OUTF / 4; e4 += 256) {
        *(float4*)&s1[e4 * 4] = *(const float4*)&q1[e4 * 4];
        *(float4*)&s2[e4 * 4] = *(const float4*)&q2[e4 * 4];
    }
    for (int e = t; e < NN * NN; e += 256) sG[e] = G[e];
    __syncthreads();

    const int ocl = t & 127;
    const int m0 = (t >> 7) * 12;
    #pragma unroll
    for (int mg = 0; mg < 3; mg++) {
        float a1[4] = {0.f, 0.f, 0.f, 0.f};
        float a2[4] = {0.f, 0.f, 0.f, 0.f};
        int mb = m0 + mg * 4;
        for (int n = 0; n < NN; n++) {
            float v1 = s1[n * OUTF + ocl];
            float v2 = s2[n * OUTF + ocl];
            #pragma unroll
            for (int j = 0; j < 4; j++) {
                float w = sG[(mb + j) * NN + n];
                a1[j] += w * v1; a2[j] += w * v2;
            }
        }
        #pragma unroll
        for (int j = 0; j < 4; j++) {
            long idx = ((long)b * NN + mb + j) * OUTF + ocl;
            o1[idx] = tanhf(a1[j]);
            o2[idx] = tanhf(a2[j]);
        }
    }
}

// ---------------- fast init mix: h0/c0 into both LSTM states ----------------
__global__ __launch_bounds__(256) void k_mix_init_f(
    const float* __restrict__ p1, const float* __restrict__ p2,
    const float* __restrict__ G)
{
    __shared__ float s1[NN * OUTF];
    __shared__ float s2[NN * OUTF];
    __shared__ float sG[NN * NN];
    const int b = blockIdx.x;
    const int t = threadIdx.x;
    const float* q1 = p1 + (long)b * NN * OUTF;
    const float* q2 = p2 + (long)b * NN * OUTF;
    for (int e4 = t; e4 < NN * OUTF / 4; e4 += 256) {
        *(float4*)&s1[e4 * 4] = *(const float4*)&q1[e4 * 4];
        *(float4*)&s2[e4 * 4] = *(const float4*)&q2[e4 * 4];
    }
    for (int e = t; e < NN * NN; e += 256) sG[e] = G[e];
    __syncthreads();

    const int ocl = t & 127;
    const int m0 = (t >> 7) * 12;
    #pragma unroll
    for (int mg = 0; mg < 3; mg++) {
        float a1[4] = {0.f, 0.f, 0.f, 0.f};
        float a2[4] = {0.f, 0.f, 0.f, 0.f};
        int mb = m0 + mg * 4;
        for (int n = 0; n < NN; n++) {
            float v1 = s1[n * OUTF + ocl];
            float v2 = s2[n * OUTF + ocl];
            #pragma unroll
            for (int j = 0; j < 4; j++) {
                float w = sG[(mb + j) * NN + n];
                a1[j] += w * v1; a2[j] += w * v2;
            }
        }
        #pragma unroll
        for (int j = 0; j < 4; j++) {
            long idx = ((long)b * NN + mb + j) * OUTF + ocl;
            g_h1[idx] = a1[j]; g_h2[idx] = a1[j];
            g_c1[idx] = a2[j]; g_c2[idx] = a2[j];
        }
    }
}

// ---------------- init xi / loc_start ----------------
__global__ void k_init_xi(const float* __restrict__ x, const float* __restrict__ z)
{
    int idx = blockIdx.x * blockDim.x + threadIdx.x;
    if (idx >= BB * NN * XIF) return;
    int j = idx % XIF;
    int bn = idx / XIF;
    float v;
    if (j < LL) {
        v = z[(long)bn * LL + j];
    } else {
        v = x[(long)bn * IN_F + (j - LL)];
        if (j < LL + 4) g_ls[(long)bn * 4 + (j - LL)] = v;
    }
    g_xi[idx] = v;
}

// ---------------- per-(b,n) head pre-projection: [3 loc | 4 logz] ----------------
__global__ __launch_bounds__(128) void k_head_pre(
    const float* __restrict__ locW, const float* __restrict__ logzW)
{
    int w = blockIdx.x * 4 + (threadIdx.x >> 5);
    int lane = threadIdx.x & 31;
    long base = (long)w * OUTF + lane * 4;
    float4 v1 = *reinterpret_cast<const float4*>(&g_yi1[base]);
    float4 v2 = *reinterpret_cast<const float4*>(&g_yi2[base]);
    float a[7] = {0.f, 0.f, 0.f, 0.f, 0.f, 0.f, 0.f};
    float x1[4] = {v1.x, v1.y, v1.z, v1.w};
    float x2[4] = {v2.x, v2.y, v2.z, v2.w};
    #pragma unroll
    for (int j = 0; j < 4; j++) {
        int f = lane * 4 + j;
        a[0] += x1[j] * locW[f * 3 + 0];
        a[1] += x1[j] * locW[f * 3 + 1];
        a[2] += x1[j] * locW[f * 3 + 2];
        a[3] += x2[j] * logzW[f * 4 + 0];
        a[4] += x2[j] * logzW[f * 4 + 1];
        a[5] += x2[j] * logzW[f * 4 + 2];
        a[6] += x2[j] * logzW[f * 4 + 3];
    }
    #pragma unroll
    for (int s = 16; s > 0; s >>= 1)
        #pragma unroll
        for (int k = 0; k < 7; k++)
            a[k] += __shfl_xor_sync(0xFFFFFFFFu, a[k], s);
    if (lane == 0) {
        #pragma unroll
        for (int k = 0; k < 7; k++) g_hp[(long)w * 8 + k] = a[k];
    }
}

// ---------------- final: G-mix head, normalize, quat-mul, outputs, next xi ----------------
__global__ __launch_bounds__(64) void k_final(
    const float* __restrict__ G,
    const float* __restrict__ locb, const float* __restrict__ logzb,
    float* __restrict__ out, int t)
{
    const int b = blockIdx.x;
    const int tid = threadIdx.x;
    __shared__ float hps[NN][8];
    for (int e = tid; e < NN * 8; e += 64)
        (&hps[0][0])[e] = g_hp[(long)b * NN * 8 + e];
    __syncthreads();
    if (tid < NN) {
        const int m = tid;
        float l0 = locb[0], l1 = locb[1], l2 = locb[2];
        float z0 = logzb[0], z1 = logzb[1], z2 = logzb[2], z3 = logzb[3];
        #pragma unroll 4
        for (int n = 0; n < NN; n++) {
            float w = G[m * NN + n];
            l0 += w * hps[n][0]; l1 += w * hps[n][1]; l2 += w * hps[n][2];
            z0 += w * hps[n][3]; z1 += w * hps[n][4];
            z2 += w * hps[n][5]; z3 += w * hps[n][6];
        }
        float r = rsqrtf(1.0f + l0 * l0 + l1 * l1 + l2 * l2);
        float d0 = r, d1 = l0 * r, d2 = l1 * r, d3 = l2 * r;
        float* ls = &g_ls[((long)b * NN + m) * 4];
        float w1 = ls[0], x1 = ls[1], y1 = ls[2], zz1 = ls[3];
        float q0 = w1 * d0 - x1 * d1 - y1 * d2 - zz1 * d3;
        float q1 = w1 * d1 + x1 * d0 + y1 * d3 - zz1 * d2;
        float q2 = w1 * d2 - x1 * d3 + y1 * d0 + zz1 * d1;
        float q3 = w1 * d3 + x1 * d2 - y1 * d1 + zz1 * d0;
        ls[0] = q0; ls[1] = q1; ls[2] = q2; ls[3] = q3;
        long ob = (((long)b * TT + t) * NN + m) * 4;
        out[ob + 0] = q0; out[ob + 1] = q1; out[ob + 2] = q2; out[ob + 3] = q3;
        const long ZOFF = (long)BB * TT * NN * 4;
        out[ZOFF + ob + 0] = z0; out[ZOFF + ob + 1] = z1;
        out[ZOFF + ob + 2] = z2; out[ZOFF + ob + 3] = z3;
        float* xr = &g_xi[((long)b * NN + m) * XIF];
        xr[64] = q0; xr[65] = q1; xr[66] = q2; xr[67] = q3;
        xr[68] = d0; xr[69] = d1; xr[70] = d2; xr[71] = d3;
    }
}

// ---------------- host ----------------
extern "C" void kernel_launch(void* const* d_in, const int* in_sizes, int n_in,
                              void* d_out, int out_size)
{
    const float* x     = (const float*)d_in[0];
    const float* enc   = (const float*)d_in[1];
    const float* z     = (const float*)d_in[2];
    /* d_in[3] = y, unused by the reference */
    const float* G     = (const float*)d_in[4];
    const float* Wx0   = (const float*)d_in[5];
    const float* Wh0   = (const float*)d_in[6];
    const float* b0    = (const float*)d_in[7];
    const float* Wx1   = (const float*)d_in[8];
    const float* Wh1   = (const float*)d_in[9];
    const float* b1    = (const float*)d_in[10];
    const float* fcW   = (const float*)d_in[11];
    const float* fcb   = (const float*)d_in[12];
    const float* fc2W  = (const float*)d_in[13];
    const float* fc2b  = (const float*)d_in[14];
    const float* ih1W  = (const float*)d_in[15];
    const float* ih1b  = (const float*)d_in[16];
    const float* ih2W  = (const float*)d_in[17];
    const float* ih2b  = (const float*)d_in[18];
    const float* locW  = (const float*)d_in[19];
    const float* locb  = (const float*)d_in[20];
    const float* logzW = (const float*)d_in[21];
    const float* logzb = (const float*)d_in[22];
    float* out = (float*)d_out;

    float *xi, *h1, *c1, *h2, *c2, *gts, *p1, *p2, *yi, *yi1, *yi2;
    cudaGetSymbolAddress((void**)&xi,  g_xi);
    cudaGetSymbolAddress((void**)&h1,  g_h1);
    cudaGetSymbolAddress((void**)&c1,  g_c1);
    cudaGetSymbolAddress((void**)&h2,  g_h2);
    cudaGetSymbolAddress((void**)&c2,  g_c2);
    cudaGetSymbolAddress((void**)&gts, g_gts);
    cudaGetSymbolAddress((void**)&p1,  g_p1);
    cudaGetSymbolAddress((void**)&p2,  g_p2);
    cudaGetSymbolAddress((void**)&yi,  g_yi);
    cudaGetSymbolAddress((void**)&yi1, g_yi1);
    cudaGetSymbolAddress((void**)&yi2, g_yi2);

    // ---- init ----
    {
        int tot = BB * NN * XIF;
        k_init_xi<<<(tot + 255) / 256, 256>>>(x, z);
    }
    // fused: enc @ ih1_W -> p1 (z=0) and enc @ ih2_W -> p2 (z=1)
    {
        dim3 grid(1, (BB * NN) / BMX, 2);
        gemm128<<<grid, 256>>>(enc, 0, HH, HH,
                               enc, 0, HH, 0,
                               ih1W, ih2W, 0,
                               ih1W, 0,
                               ih1b, ih2b, 0,
                               p1, p2, 0, OUTF, OUTF, 1);
    }
    k_mix_init_f<<<BB, 256>>>(p1, p2, G);

    // ---- T sequential steps ----
    for (int t = 0; t < TT; t++) {
        // LSTM1 gates: xi @ Wx0[n] + h1 @ Wh0[n] + b0[n]
        {
            dim3 grid(G4 / BNX, BB / BMX, NN);
            gemm128<<<grid, 256>>>(xi, XIF, NN * XIF, XIF,
                                   h1, OUTF, NN * OUTF, OUTF,
                                   Wx0, Wx0, (long)XIF * G4,
                                   Wh0, (long)OUTF * G4,
                                   b0, b0, G4,
                                   gts, gts, G4, NN * G4, G4, NN);
        }
        { dim3 grid(2, BB); k_mix_lstm_f<<<grid, 256>>>(gts, G, h1, c1, nullptr); }
        // LSTM2 gates: h1 @ Wx1[n] + h2 @ Wh1[n] + b1[n]
        {
            dim3 grid(G4 / BNX, BB / BMX, NN);
            gemm128<<<grid, 256>>>(h1, OUTF, NN * OUTF, OUTF,
                                   h2, OUTF, NN * OUTF, OUTF,
                                   Wx1, Wx1, (long)OUTF * G4,
                                   Wh1, (long)OUTF * G4,
                                   b1, b1, G4,
                                   gts, gts, G4, NN * G4, G4, NN);
        }
        { dim3 grid(2, BB); k_mix_lstm_f<<<grid, 256>>>(gts, G, h2, c2, yi); }
        // fused fc / fc2: yi @ fc_W[n] -> p1 (z<24), yi @ fc2_W[n] -> p2 (z>=24)
        {
            dim3 grid(1, BB / BMX, 2 * NN);
            gemm128<<<grid, 256>>>(yi, OUTF, NN * OUTF, OUTF,
                                   yi, OUTF, NN * OUTF, 0,
                                   fcW, fc2W, (long)OUTF * OUTF,
                                   fcW, 0,
                                   fcb, fc2b, OUTF,
                                   p1, p2, OUTF, NN * OUTF, OUTF, NN);
        }
        k_mix_tanh2_f<<<BB, 256>>>(p1, p2, G, yi1, yi2);
        // head projections + finalize
        k_head_pre<<<(BB * NN) / 4, 128>>>(locW, logzW);
        k_final<<<BB, 64>>>(G, locb, logzb, out, t);
    }
}

// round 5
// speedup vs baseline: 1.9653x; 1.0735x over previous
#include <cuda_runtime.h>
#include <math.h>

#define BB 512
#define NN 24
#define TT 25
#define IN_F 8
#define LL 64
#define HH 256
#define OUTF 128
#define XIF 72
#define G4 512

typedef unsigned int uint32;

// ---------------- scratch (device globals; allocation-free) ----------------
__device__ float g_xi [BB*NN*XIF];
__device__ float g_h1 [BB*NN*OUTF];
__device__ float g_c1 [BB*NN*OUTF];
__device__ float g_h2 [BB*NN*OUTF];
__device__ float g_c2 [BB*NN*OUTF];
__device__ float g_gts[BB*NN*G4];
__device__ float g_p1 [BB*NN*OUTF];
__device__ float g_p2 [BB*NN*OUTF];
__device__ float g_yi [BB*NN*OUTF];
__device__ float g_yi1[BB*NN*OUTF];
__device__ float g_yi2[BB*NN*OUTF];
__device__ float g_hp [BB*NN*8];
__device__ float g_ls [BB*NN*4];

__device__ __forceinline__ float sigf(float v) { return 1.0f / (1.0f + expf(-v)); }

__device__ __forceinline__ uint32 cvt_tf32(float f) {
    uint32 u; asm("cvt.rna.tf32.f32 %0, %1;" : "=r"(u) : "f"(f)); return u;
}
__device__ __forceinline__ void split_tf32(float v, uint32& hi, uint32& lo) {
    uint32 h = cvt_tf32(v);
    hi = h;
    lo = cvt_tf32(v - __uint_as_float(h));
}

__device__ __forceinline__ void mma_tf32(
    float& d0, float& d1, float& d2, float& d3,
    uint32 a0, uint32 a1, uint32 a2, uint32 a3, uint32 b0, uint32 b1)
{
    asm volatile(
        "mma.sync.aligned.m16n8k8.row.col.f32.tf32.tf32.f32 "
        "{%0,%1,%2,%3}, {%4,%5,%6,%7}, {%8,%9}, {%0,%1,%2,%3};"
        : "+f"(d0), "+f"(d1), "+f"(d2), "+f"(d3)
        : "r"(a0), "r"(a1), "r"(a2), "r"(a3), "r"(b0), "r"(b1));
}

// ---------------- 3xTF32 tensor-core GEMM: 128x128 block, 8 warps ----------------
// K-chunk = 16. As (hi/lo): [128][20], Bs (hi/lo): [16][136]. ~37 KB smem.
#define AP 20
#define BP 136

__device__ __forceinline__ void tc3_phase(
    const float* __restrict__ A, int lda, int K,
    const float* __restrict__ W, int ldw, int col0, int row0,
    int t, uint32* AsH, uint32* AsL, uint32* BsH, uint32* BsL,
    float (&acc)[4][4][4], int wm, int wn, int g, int tg)
{
    const int nch = (K + 15) >> 4;
    // A loader: 128 rows x 4 float4 (16 k) = 512 f4 / chunk, 2 per thread
    const int ar0 = t >> 2, akc = (t & 3) * 4;           // + i*64 rows
    // B loader: 16 k-rows x 32 float4 = 512 f4 / chunk, 2 per thread
    const int bk0 = t >> 5, bc = (t & 31) * 4;           // + i*8 k-rows
    float4 pa[2], pb[2];

    // prefetch chunk 0
    #pragma unroll
    for (int i = 0; i < 2; i++) {
        int k = akc;
        pa[i] = (k < K)
            ? *(const float4*)&A[(long)(row0 + ar0 + i * 64) * lda + k]
            : make_float4(0.f, 0.f, 0.f, 0.f);
        int kr = bk0 + i * 8;
        pb[i] = (kr < K)
            ? *(const float4*)&W[(long)kr * ldw + col0 + bc]
            : make_float4(0.f, 0.f, 0.f, 0.f);
    }

    for (int c = 0; c < nch; c++) {
        __syncthreads();
        #pragma unroll
        for (int i = 0; i < 2; i++) {
            uint4 vh, vl;
            split_tf32(pa[i].x, vh.x, vl.x);
            split_tf32(pa[i].y, vh.y, vl.y);
            split_tf32(pa[i].z, vh.z, vl.z);
            split_tf32(pa[i].w, vh.w, vl.w);
            *(uint4*)&AsH[(ar0 + i * 64) * AP + akc] = vh;
            *(uint4*)&AsL[(ar0 + i * 64) * AP + akc] = vl;
            split_tf32(pb[i].x, vh.x, vl.x);
            split_tf32(pb[i].y, vh.y, vl.y);
            split_tf32(pb[i].z, vh.z, vl.z);
            split_tf32(pb[i].w, vh.w, vl.w);
            *(uint4*)&BsH[(bk0 + i * 8) * BP + bc] = vh;
            *(uint4*)&BsL[(bk0 + i * 8) * BP + bc] = vl;
        }
        __syncthreads();

        if (c + 1 < nch) {
            int k0 = (c + 1) * 16;
            #pragma unroll
            for (int i = 0; i < 2; i++) {
                int k = k0 + akc;
                pa[i] = (k < K)
                    ? *(const float4*)&A[(long)(row0 + ar0 + i * 64) * lda + k]
                    : make_float4(0.f, 0.f, 0.f, 0.f);
                int kr = k0 + bk0 + i * 8;
                pb[i] = (kr < K)
                    ? *(const float4*)&W[(long)kr * ldw + col0 + bc]
                    : make_float4(0.f, 0.f, 0.f, 0.f);
            }
        }

        #pragma unroll
        for (int k8 = 0; k8 < 2; k8++) {
            const int kk = k8 * 8;
            uint32 afh[4][4], afl[4][4];
            #pragma unroll
            for (int i = 0; i < 4; i++) {
                const uint32* aph = &AsH[(wm * 64 + i * 16 + g) * AP + kk + tg];
                const uint32* apl = &AsL[(wm * 64 + i * 16 + g) * AP + kk + tg];
                afh[i][0] = aph[0];  afh[i][1] = aph[8 * AP];
                afh[i][2] = aph[4];  afh[i][3] = aph[8 * AP + 4];
                afl[i][0] = apl[0];  afl[i][1] = apl[8 * AP];
                afl[i][2] = apl[4];  afl[i][3] = apl[8 * AP + 4];
            }
            #pragma unroll
            for (int j = 0; j < 4; j++) {
                int ncol = wn * 32 + j * 8 + g;
                const uint32* bph = &BsH[(kk + tg) * BP + ncol];
                const uint32* bpl = &BsL[(kk + tg) * BP + ncol];
                uint32 bh0 = bph[0], bh1 = bph[4 * BP];
                uint32 bl0 = bpl[0], bl1 = bpl[4 * BP];
                #pragma unroll
                for (int i = 0; i < 4; i++) {
                    mma_tf32(acc[i][j][0], acc[i][j][1], acc[i][j][2], acc[i][j][3],
                             afh[i][0], afh[i][1], afh[i][2], afh[i][3], bl0, bl1);
                    mma_tf32(acc[i][j][0], acc[i][j][1], acc[i][j][2], acc[i][j][3],
                             afl[i][0], afl[i][1], afl[i][2], afl[i][3], bh0, bh1);
                    mma_tf32(acc[i][j][0], acc[i][j][1], acc[i][j][2], acc[i][j][3],
                             afh[i][0], afh[i][1], afh[i][2], afh[i][3], bh0, bh1);
                }
            }
        }
    }
    __syncthreads();
}

// C[node] = A1[node] @ W1[node] (+ A2[node] @ W2[node]) + bias[node]
// blocks with blockIdx.z >= nodes use the "alt" weight/bias/output set.
__global__ __launch_bounds__(256) void gemm_tc3(
    const float* __restrict__ A1, long a1n, int lda1, int K1,
    const float* __restrict__ A2, long a2n, int lda2, int K2,
    const float* __restrict__ W1, const float* __restrict__ W1b, long w1n,
    const float* __restrict__ W2, long w2n,
    const float* __restrict__ bias, const float* __restrict__ biasb, long bn,
    float* __restrict__ C, float* __restrict__ Cb, long cn, int ldc, int O, int nodes)
{
    __shared__ uint32 AsH[128 * AP];
    __shared__ uint32 AsL[128 * AP];
    __shared__ uint32 BsH[16 * BP];
    __shared__ uint32 BsL[16 * BP];

    int z = blockIdx.z, node = z;
    const float* w1 = W1; const float* bsrc = bias; float* c = C;
    if (z >= nodes) { node = z - nodes; w1 = W1b; bsrc = biasb; c = Cb; }

    const int t = threadIdx.x;
    const int w = t >> 5, lane = t & 31;
    const int wm = w >> 2, wn = w & 3;
    const int g = lane >> 2, tg = lane & 3;
    const int row0 = blockIdx.y * 128;
    const int col0 = blockIdx.x * 128;

    float acc[4][4][4];
    #pragma unroll
    for (int i = 0; i < 4; i++)
        #pragma unroll
        for (int j = 0; j < 4; j++)
            #pragma unroll
            for (int r = 0; r < 4; r++) acc[i][j][r] = 0.f;

    tc3_phase(A1 + (long)node * a1n, lda1, K1, w1 + (long)node * w1n, O, col0,
              row0, t, AsH, AsL, BsH, BsL, acc, wm, wn, g, tg);
    if (K2 > 0)
        tc3_phase(A2 + (long)node * a2n, lda2, K2, W2 + (long)node * w2n, O, col0,
                  row0, t, AsH, AsL, BsH, BsL, acc, wm, wn, g, tg);

    const float* bp = bsrc + (long)node * bn;
    float* cbase = c + (long)node * cn;
    #pragma unroll
    for (int j = 0; j < 4; j++) {
        int col = col0 + wn * 32 + j * 8 + tg * 2;
        float2 bv = *(const float2*)&bp[col];
        #pragma unroll
        for (int i = 0; i < 4; i++) {
            int r = row0 + wm * 64 + i * 16 + g;
            float2 v0 = make_float2(acc[i][j][0] + bv.x, acc[i][j][1] + bv.y);
            float2 v1 = make_float2(acc[i][j][2] + bv.x, acc[i][j][3] + bv.y);
            *(float2*)&cbase[(long)r * ldc + col] = v0;
            *(float2*)&cbase[(long)(r + 8) * ldc + col] = v1;
        }
    }
}

// ---------------- fast G-mix + LSTM pointwise ----------------
// grid (2, 512): blockIdx.x = oc-half (64 ch), blockIdx.y = b. 256 threads.
__global__ __launch_bounds__(256) void k_mix_lstm_f(
    const float* __restrict__ gp, const float* __restrict__ G,
    float* __restrict__ h, float* __restrict__ c, float* __restrict__ yi)
{
    __shared__ float sg[NN * 256];   // [n][gate*64 + ocl]
    __shared__ float sG[NN * NN];
    const int och = blockIdx.x, b = blockIdx.y;
    const int t = threadIdx.x;
    const float* src = gp + (long)b * NN * G4;
    for (int e4 = t; e4 < NN * 256 / 4; e4 += 256) {
        int e = e4 * 4;
        int n = e >> 8, col = e & 255, g = col >> 6, j = col & 63;
        *(float4*)&sg[e] = *(const float4*)&src[n * G4 + g * 128 + och * 64 + j];
    }
    for (int e = t; e < NN * NN; e += 256) sG[e] = G[e];
    __syncthreads();

    const int ocl = t & 63;
    const int m0 = (t >> 6) * 6;
    float acc[6][4];
    #pragma unroll
    for (int j = 0; j < 6; j++)
        #pragma unroll
        for (int g = 0; g < 4; g++) acc[j][g] = 0.f;
    for (int n = 0; n < NN; n++) {
        float gv0 = sg[n * 256 + ocl];
        float gv1 = sg[n * 256 + 64 + ocl];
        float gv2 = sg[n * 256 + 128 + ocl];
        float gv3 = sg[n * 256 + 192 + ocl];
        #pragma unroll
        for (int j = 0; j < 6; j++) {
            float w = sG[(m0 + j) * NN + n];
            acc[j][0] += w * gv0; acc[j][1] += w * gv1;
            acc[j][2] += w * gv2; acc[j][3] += w * gv3;
        }
    }
    const int oc = och * 64 + ocl;
    #pragma unroll
    for (int j = 0; j < 6; j++) {
        long idx = ((long)b * NN + m0 + j) * OUTF + oc;
        float cc = sigf(acc[j][1]) * c[idx] + sigf(acc[j][0]) * tanhf(acc[j][2]);
        float hh = sigf(acc[j][3]) * tanhf(cc);
        c[idx] = cc;
        h[idx] = hh;
        if (yi) yi[idx] = tanhf(hh);
    }
}

// ---------------- fast G-mix + tanh for fc branches ----------------
__global__ __launch_bounds__(256) void k_mix_tanh2_f(
    const float* __restrict__ p1, const float* __restrict__ p2,
    const float* __restrict__ G,
    float* __restrict__ o1, float* __restrict__ o2)
{
    __shared__ float s1[NN * OUTF];
    __shared__ float s2[NN * OUTF];
    __shared__ float sG[NN * NN];
    const int b = blockIdx.x;
    const int t = threadIdx.x;
    const float* q1 = p1 + (long)b * NN * OUTF;
    const float* q2 = p2 + (long)b * NN * OUTF;
    for (int e4 = t; e4 < NN * OUTF / 4; e4 += 256) {
        *(float4*)&s1[e4 * 4] = *(const float4*)&q1[e4 * 4];
        *(float4*)&s2[e4 * 4] = *(const float4*)&q2[e4 * 4];
    }
    for (int e = t; e < NN * NN; e += 256) sG[e] = G[e];
    __syncthreads();

    const int ocl = t & 127;
    const int m0 = (t >> 7) * 12;
    #pragma unroll
    for (int mg = 0; mg < 3; mg++) {
        float a1[4] = {0.f, 0.f, 0.f, 0.f};
        float a2[4] = {0.f, 0.f, 0.f, 0.f};
        int mb = m0 + mg * 4;
        for (int n = 0; n < NN; n++) {
            float v1 = s1[n * OUTF + ocl];
            float v2 = s2[n * OUTF + ocl];
            #pragma unroll
            for (int j = 0; j < 4; j++) {
                float w = sG[(mb + j) * NN + n];
                a1[j] += w * v1; a2[j] += w * v2;
            }
        }
        #pragma unroll
        for (int j = 0; j < 4; j++) {
            long idx = ((long)b * NN + mb + j) * OUTF + ocl;
            o1[idx] = tanhf(a1[j]);
            o2[idx] = tanhf(a2[j]);
        }
    }
}

// ---------------- fast init mix: h0/c0 into both LSTM states ----------------
__global__ __launch_bounds__(256) void k_mix_init_f(
    const float* __restrict__ p1, const float* __restrict__ p2,
    const float* __restrict__ G)
{
    __shared__ float s1[NN * OUTF];
    __shared__ float s2[NN * OUTF];
    __shared__ float sG[NN * NN];
    const int b = blockIdx.x;
    const int t = threadIdx.x;
    const float* q1 = p1 + (long)b * NN * OUTF;
    const float* q2 = p2 + (long)b * NN * OUTF;
    for (int e4 = t; e4 < NN * OUTF / 4; e4 += 256) {
        *(float4*)&s1[e4 * 4] = *(const float4*)&q1[e4 * 4];
        *(float4*)&s2[e4 * 4] = *(const float4*)&q2[e4 * 4];
    }
    for (int e = t; e < NN * NN; e += 256) sG[e] = G[e];
    __syncthreads();

    const int ocl = t & 127;
    const int m0 = (t >> 7) * 12;
    #pragma unroll
    for (int mg = 0; mg < 3; mg++) {
        float a1[4] = {0.f, 0.f, 0.f, 0.f};
        float a2[4] = {0.f, 0.f, 0.f, 0.f};
        int mb = m0 + mg * 4;
        for (int n = 0; n < NN; n++) {
            float v1 = s1[n * OUTF + ocl];
            float v2 = s2[n * OUTF + ocl];
            #pragma unroll
            for (int j = 0; j < 4; j++) {
                float w = sG[(mb + j) * NN + n];
                a1[j] += w * v1; a2[j] += w * v2;
            }
        }
        #pragma unroll
        for (int j = 0; j < 4; j++) {
            long idx = ((long)b * NN + mb + j) * OUTF + ocl;
            g_h1[idx] = a1[j]; g_h2[idx] = a1[j];
            g_c1[idx] = a2[j]; g_c2[idx] = a2[j];
        }
    }
}

// ---------------- init xi / loc_start ----------------
__global__ void k_init_xi(const float* __restrict__ x, const float* __restrict__ z)
{
    int idx = blockIdx.x * blockDim.x + threadIdx.x;
    if (idx >= BB * NN * XIF) return;
    int j = idx % XIF;
    int bn = idx / XIF;
    float v;
    if (j < LL) {
        v = z[(long)bn * LL + j];
    } else {
        v = x[(long)bn * IN_F + (j - LL)];
        if (j < LL + 4) g_ls[(long)bn * 4 + (j - LL)] = v;
    }
    g_xi[idx] = v;
}

// ---------------- per-(b,n) head pre-projection: [3 loc | 4 logz] ----------------
__global__ __launch_bounds__(128) void k_head_pre(
    const float* __restrict__ locW, const float* __restrict__ logzW)
{
    int w = blockIdx.x * 4 + (threadIdx.x >> 5);
    int lane = threadIdx.x & 31;
    long base = (long)w * OUTF + lane * 4;
    float4 v1 = *reinterpret_cast<const float4*>(&g_yi1[base]);
    float4 v2 = *reinterpret_cast<const float4*>(&g_yi2[base]);
    float a[7] = {0.f, 0.f, 0.f, 0.f, 0.f, 0.f, 0.f};
    float x1[4] = {v1.x, v1.y, v1.z, v1.w};
    float x2[4] = {v2.x, v2.y, v2.z, v2.w};
    #pragma unroll
    for (int j = 0; j < 4; j++) {
        int f = lane * 4 + j;
        a[0] += x1[j] * locW[f * 3 + 0];
        a[1] += x1[j] * locW[f * 3 + 1];
        a[2] += x1[j] * locW[f * 3 + 2];
        a[3] += x2[j] * logzW[f * 4 + 0];
        a[4] += x2[j] * logzW[f * 4 + 1];
        a[5] += x2[j] * logzW[f * 4 + 2];
        a[6] += x2[j] * logzW[f * 4 + 3];
    }
    #pragma unroll
    for (int s = 16; s > 0; s >>= 1)
        #pragma unroll
        for (int k = 0; k < 7; k++)
            a[k] += __shfl_xor_sync(0xFFFFFFFFu, a[k], s);
    if (lane == 0) {
        #pragma unroll
        for (int k = 0; k < 7; k++) g_hp[(long)w * 8 + k] = a[k];
    }
}

// ---------------- final: G-mix head, normalize, quat-mul, outputs, next xi ----------------
__global__ __launch_bounds__(64) void k_final(
    const float* __restrict__ G,
    const float* __restrict__ locb, const float* __restrict__ logzb,
    float* __restrict__ out, int t)
{
    const int b = blockIdx.x;
    const int tid = threadIdx.x;
    __shared__ float hps[NN][8];
    for (int e = tid; e < NN * 8; e += 64)
        (&hps[0][0])[e] = g_hp[(long)b * NN * 8 + e];
    __syncthreads();
    if (tid < NN) {
        const int m = tid;
        float l0 = locb[0], l1 = locb[1], l2 = locb[2];
        float z0 = logzb[0], z1 = logzb[1], z2 = logzb[2], z3 = logzb[3];
        #pragma unroll 4
        for (int n = 0; n < NN; n++) {
            float w = G[m * NN + n];
            l0 += w * hps[n][0]; l1 += w * hps[n][1]; l2 += w * hps[n][2];
            z0 += w * hps[n][3]; z1 += w * hps[n][4];
            z2 += w * hps[n][5]; z3 += w * hps[n][6];
        }
        float r = rsqrtf(1.0f + l0 * l0 + l1 * l1 + l2 * l2);
        float d0 = r, d1 = l0 * r, d2 = l1 * r, d3 = l2 * r;
        float* ls = &g_ls[((long)b * NN + m) * 4];
        float w1 = ls[0], x1 = ls[1], y1 = ls[2], zz1 = ls[3];
        float q0 = w1 * d0 - x1 * d1 - y1 * d2 - zz1 * d3;
        float q1 = w1 * d1 + x1 * d0 + y1 * d3 - zz1 * d2;
        float q2 = w1 * d2 - x1 * d3 + y1 * d0 + zz1 * d1;
        float q3 = w1 * d3 + x1 * d2 - y1 * d1 + zz1 * d0;
        ls[0] = q0; ls[1] = q1; ls[2] = q2; ls[3] = q3;
        long ob = (((long)b * TT + t) * NN + m) * 4;
        out[ob + 0] = q0; out[ob + 1] = q1; out[ob + 2] = q2; out[ob + 3] = q3;
        const long ZOFF = (long)BB * TT * NN * 4;
        out[ZOFF + ob + 0] = z0; out[ZOFF + ob + 1] = z1;
        out[ZOFF + ob + 2] = z2; out[ZOFF + ob + 3] = z3;
        float* xr = &g_xi[((long)b * NN + m) * XIF];
        xr[64] = q0; xr[65] = q1; xr[66] = q2; xr[67] = q3;
        xr[68] = d0; xr[69] = d1; xr[70] = d2; xr[71] = d3;
    }
}

// ---------------- host ----------------
extern "C" void kernel_launch(void* const* d_in, const int* in_sizes, int n_in,
                              void* d_out, int out_size)
{
    const float* x     = (const float*)d_in[0];
    const float* enc   = (const float*)d_in[1];
    const float* z     = (const float*)d_in[2];
    /* d_in[3] = y, unused by the reference */
    const float* G     = (const float*)d_in[4];
    const float* Wx0   = (const float*)d_in[5];
    const float* Wh0   = (const float*)d_in[6];
    const float* b0    = (const float*)d_in[7];
    const float* Wx1   = (const float*)d_in[8];
    const float* Wh1   = (const float*)d_in[9];
    const float* b1    = (const float*)d_in[10];
    const float* fcW   = (const float*)d_in[11];
    const float* fcb   = (const float*)d_in[12];
    const float* fc2W  = (const float*)d_in[13];
    const float* fc2b  = (const float*)d_in[14];
    const float* ih1W  = (const float*)d_in[15];
    const float* ih1b  = (const float*)d_in[16];
    const float* ih2W  = (const float*)d_in[17];
    const float* ih2b  = (const float*)d_in[18];
    const float* locW  = (const float*)d_in[19];
    const float* locb  = (const float*)d_in[20];
    const float* logzW = (const float*)d_in[21];
    const float* logzb = (const float*)d_in[22];
    float* out = (float*)d_out;

    float *xi, *h1, *c1, *h2, *c2, *gts, *p1, *p2, *yi, *yi1, *yi2;
    cudaGetSymbolAddress((void**)&xi,  g_xi);
    cudaGetSymbolAddress((void**)&h1,  g_h1);
    cudaGetSymbolAddress((void**)&c1,  g_c1);
    cudaGetSymbolAddress((void**)&h2,  g_h2);
    cudaGetSymbolAddress((void**)&c2,  g_c2);
    cudaGetSymbolAddress((void**)&gts, g_gts);
    cudaGetSymbolAddress((void**)&p1,  g_p1);
    cudaGetSymbolAddress((void**)&p2,  g_p2);
    cudaGetSymbolAddress((void**)&yi,  g_yi);
    cudaGetSymbolAddress((void**)&yi1, g_yi1);
    cudaGetSymbolAddress((void**)&yi2, g_yi2);

    // ---- init ----
    {
        int tot = BB * NN * XIF;
        k_init_xi<<<(tot + 255) / 256, 256>>>(x, z);
    }
    // fused: enc @ ih1_W -> p1 (z=0) and enc @ ih2_W -> p2 (z=1)
    {
        dim3 grid(1, (BB * NN) / 128, 2);
        gemm_tc3<<<grid, 256>>>(enc, 0, HH, HH,
                                enc, 0, HH, 0,
                                ih1W, ih2W, 0,
                                ih1W, 0,
                                ih1b, ih2b, 0,
                                p1, p2, 0, OUTF, OUTF, 1);
    }
    k_mix_init_f<<<BB, 256>>>(p1, p2, G);

    // ---- T sequential steps ----
    for (int t = 0; t < TT; t++) {
        // LSTM1 gates: xi @ Wx0[n] + h1 @ Wh0[n] + b0[n]
        {
            dim3 grid(G4 / 128, BB / 128, NN);
            gemm_tc3<<<grid, 256>>>(xi, XIF, NN * XIF, XIF,
                                    h1, OUTF, NN * OUTF, OUTF,
                                    Wx0, Wx0, (long)XIF * G4,
                                    Wh0, (long)OUTF * G4,
                                    b0, b0, G4,
                                    gts, gts, G4, NN * G4, G4, NN);
        }
        { dim3 grid(2, BB); k_mix_lstm_f<<<grid, 256>>>(gts, G, h1, c1, nullptr); }
        // LSTM2 gates: h1 @ Wx1[n] + h2 @ Wh1[n] + b1[n]
        {
            dim3 grid(G4 / 128, BB / 128, NN);
            gemm_tc3<<<grid, 256>>>(h1, OUTF, NN * OUTF, OUTF,
                                    h2, OUTF, NN * OUTF, OUTF,
                                    Wx1, Wx1, (long)OUTF * G4,
                                    Wh1, (long)OUTF * G4,
                                    b1, b1, G4,
                                    gts, gts, G4, NN * G4, G4, NN);
        }
        { dim3 grid(2, BB); k_mix_lstm_f<<<grid, 256>>>(gts, G, h2, c2, yi); }
        // fused fc / fc2: yi @ fc_W[n] -> p1 (z<24), yi @ fc2_W[n] -> p2 (z>=24)
        {
            dim3 grid(1, BB / 128, 2 * NN);
            gemm_tc3<<<grid, 256>>>(yi, OUTF, NN * OUTF, OUTF,
                                    yi, OUTF, NN * OUTF, 0,
                                    fcW, fc2W, (long)OUTF * OUTF,
                                    fcW, 0,
                                    fcb, fc2b, OUTF,
                                    p1, p2, OUTF, NN * OUTF, OUTF, NN);
        }
        k_mix_tanh2_f<<<BB, 256>>>(p1, p2, G, yi1, yi2);
        // head projections + finalize
        k_head_pre<<<(BB * NN) / 4, 128>>>(locW, logzW);
        k_final<<<BB, 64>>>(G, locb, logzb, out, t);
    }
}

// round 7
// speedup vs baseline: 2.8671x; 1.4588x over previous
#include <cuda_runtime.h>
#include <cuda_bf16.h>
#include <math.h>

#define BB 512
#define NN 24
#define TT 25
#define IN_F 8
#define LL 64
#define HH 256
#define OUTF 128
#define XIF 72
#define G4 512

typedef unsigned int uint32;

// ---------------- scratch (device globals; allocation-free) ----------------
__device__ float g_xi [BB*NN*XIF];
__device__ float g_h1 [BB*NN*OUTF];
__device__ float g_c1 [BB*NN*OUTF];
__device__ float g_h2 [BB*NN*OUTF];
__device__ float g_c2 [BB*NN*OUTF];
__device__ float g_gts[BB*NN*G4];
__device__ float g_p1 [BB*NN*OUTF];
__device__ float g_p2 [BB*NN*OUTF];
__device__ float g_yi [BB*NN*OUTF];
__device__ float g_yi1[BB*NN*OUTF];
__device__ float g_yi2[BB*NN*OUTF];
__device__ float g_hp [BB*NN*8];
__device__ float g_ls [BB*NN*4];

__device__ __forceinline__ float sigf(float v) { return 1.0f / (1.0f + expf(-v)); }

// split a pair of floats (consecutive k) into packed bf16 hi and lo words
__device__ __forceinline__ void splitpair(float a, float b, uint32& h, uint32& l) {
    __nv_bfloat16 ha = __float2bfloat16_rn(a);
    __nv_bfloat16 hb = __float2bfloat16_rn(b);
    float ra = a - __bfloat162float(ha);
    float rb = b - __bfloat162float(hb);
    __nv_bfloat162 hh; hh.x = ha; hh.y = hb;
    __nv_bfloat162 ll; ll.x = __float2bfloat16_rn(ra); ll.y = __float2bfloat16_rn(rb);
    h = *reinterpret_cast<uint32*>(&hh);
    l = *reinterpret_cast<uint32*>(&ll);
}

__device__ __forceinline__ void mma_bf16(
    float& d0, float& d1, float& d2, float& d3,
    uint32 a0, uint32 a1, uint32 a2, uint32 a3, uint32 b0, uint32 b1)
{
    asm volatile(
        "mma.sync.aligned.m16n8k16.row.col.f32.bf16.bf16.f32 "
        "{%0,%1,%2,%3}, {%4,%5,%6,%7}, {%8,%9}, {%0,%1,%2,%3};"
        : "+f"(d0), "+f"(d1), "+f"(d2), "+f"(d3)
        : "r"(a0), "r"(a1), "r"(a2), "r"(a3), "r"(b0), "r"(b1));
}

// ---------------- bf16x2-split tensor-core GEMM ----------------
// 128x128 block, 8 warps (2x4), 64x32 warp tile, K-chunk 16, double-buffered.
// A words: [row][kp] pitch AP (kp = k/2, 8 used). B words: [kp][n] pitch BP.
#define KC 16
#define AP 12
#define BP 136
#define ASZ (128 * AP)
#define BSZ (8 * BP)

__device__ __forceinline__ void bf_phase(
    const float* __restrict__ A, int lda, int K,
    const float* __restrict__ W, int ldw, int col0, int row0,
    int t, uint32* AsH, uint32* AsL, uint32* BsH, uint32* BsL,
    float (&acc)[4][4][4], int wm, int wn, int g, int tg)
{
    const int nch = (K + KC - 1) / KC;
    // A staging: row = t>>1, k-offset (t&1)*8 floats (two float4s)
    const int arow = t >> 1, akp0 = (t & 1) * 4;   // word (k-pair) offset
    // B staging: kp = t>>5, n = (t&31)*4
    const int bkp = t >> 5, bn = (t & 31) * 4;
    const float4 z4 = make_float4(0.f, 0.f, 0.f, 0.f);
    float4 a0, a1, b0, b1;

    // base pointers for this thread's gmem stream (advance by KC / KC*ldw per chunk)
    const float* aptr = &A[(long)(row0 + arow) * lda + akp0 * 2];
    const float* bptr = &W[(long)(2 * bkp) * ldw + col0 + bn];
    int ka = akp0 * 2;          // current k of A loads
    int kb = 2 * bkp;           // current k of B loads

    // gmem load for chunk 0
    {
        bool va = (ka < K);
        a0 = va ? *(const float4*)aptr : z4;
        a1 = va ? *(const float4*)(aptr + 4) : z4;
        bool vb = (kb < K);
        b0 = vb ? *(const float4*)bptr : z4;
        b1 = vb ? *(const float4*)(bptr + ldw) : z4;
    }
    // store chunk 0 into buffer 0
    {
        uint4 h, l;
        splitpair(a0.x, a0.y, h.x, l.x); splitpair(a0.z, a0.w, h.y, l.y);
        splitpair(a1.x, a1.y, h.z, l.z); splitpair(a1.z, a1.w, h.w, l.w);
        *(uint4*)&AsH[arow * AP + akp0] = h;
        *(uint4*)&AsL[arow * AP + akp0] = l;
        splitpair(b0.x, b1.x, h.x, l.x); splitpair(b0.y, b1.y, h.y, l.y);
        splitpair(b0.z, b1.z, h.z, l.z); splitpair(b0.w, b1.w, h.w, l.w);
        *(uint4*)&BsH[bkp * BP + bn] = h;
        *(uint4*)&BsL[bkp * BP + bn] = l;
    }
    __syncthreads();

    for (int c = 0; c < nch; c++) {
        const int buf = c & 1;
        uint32* ah_s = AsH + buf * ASZ;
        uint32* al_s = AsL + buf * ASZ;
        uint32* bh_s = BsH + buf * BSZ;
        uint32* bl_s = BsL + buf * BSZ;

        if (c + 1 < nch) {    // prefetch next chunk from gmem
            aptr += KC;
            bptr += (long)KC * ldw;
            ka += KC;
            kb += KC;
            bool va = (ka < K);
            a0 = va ? *(const float4*)aptr : z4;
            a1 = va ? *(const float4*)(aptr + 4) : z4;
            bool vb = (kb < K);
            b0 = vb ? *(const float4*)bptr : z4;
            b1 = vb ? *(const float4*)(bptr + ldw) : z4;
        }

        // fragments + MMA (one k16 step)
        uint32 ah[4][4], al[4][4];
        #pragma unroll
        for (int i = 0; i < 4; i++) {
            int base = (wm * 64 + i * 16 + g) * AP;
            ah[i][0] = ah_s[base + tg];
            ah[i][1] = ah_s[base + 8 * AP + tg];
            ah[i][2] = ah_s[base + tg + 4];
            ah[i][3] = ah_s[base + 8 * AP + tg + 4];
            al[i][0] = al_s[base + tg];
            al[i][1] = al_s[base + 8 * AP + tg];
            al[i][2] = al_s[base + tg + 4];
            al[i][3] = al_s[base + 8 * AP + tg + 4];
        }
        #pragma unroll
        for (int j = 0; j < 4; j++) {
            int nc = wn * 32 + j * 8 + g;
            uint32 bh0 = bh_s[tg * BP + nc];
            uint32 bh1 = bh_s[(tg + 4) * BP + nc];
            uint32 bl0 = bl_s[tg * BP + nc];
            uint32 bl1 = bl_s[(tg + 4) * BP + nc];
            #pragma unroll
            for (int i = 0; i < 4; i++) {
                mma_bf16(acc[i][j][0], acc[i][j][1], acc[i][j][2], acc[i][j][3],
                         ah[i][0], ah[i][1], ah[i][2], ah[i][3], bh0, bh1);
                mma_bf16(acc[i][j][0], acc[i][j][1], acc[i][j][2], acc[i][j][3],
                         ah[i][0], ah[i][1], ah[i][2], ah[i][3], bl0, bl1);
                mma_bf16(acc[i][j][0], acc[i][j][1], acc[i][j][2], acc[i][j][3],
                         al[i][0], al[i][1], al[i][2], al[i][3], bh0, bh1);
            }
        }

        if (c + 1 < nch) {    // store next chunk into other buffer
            uint32* nah = AsH + (1 - buf) * ASZ;
            uint32* nal = AsL + (1 - buf) * ASZ;
            uint32* nbh = BsH + (1 - buf) * BSZ;
            uint32* nbl = BsL + (1 - buf) * BSZ;
            uint4 h, l;
            splitpair(a0.x, a0.y, h.x, l.x); splitpair(a0.z, a0.w, h.y, l.y);
            splitpair(a1.x, a1.y, h.z, l.z); splitpair(a1.z, a1.w, h.w, l.w);
            *(uint4*)&nah[arow * AP + akp0] = h;
            *(uint4*)&nal[arow * AP + akp0] = l;
            splitpair(b0.x, b1.x, h.x, l.x); splitpair(b0.y, b1.y, h.y, l.y);
            splitpair(b0.z, b1.z, h.z, l.z); splitpair(b0.w, b1.w, h.w, l.w);
            *(uint4*)&nbh[bkp * BP + bn] = h;
            *(uint4*)&nbl[bkp * BP + bn] = l;
            __syncthreads();
        }
    }
    __syncthreads();   // protect buffers before a following phase restarts
}

// C[node] = A1[node] @ W1[node] (+ A2[node] @ W2[node]) + bias[node]
// blocks with blockIdx.z >= nodes use the "alt" weight/bias/output set.
__global__ __launch_bounds__(256) void gemm_bf(
    const float* __restrict__ A1, long a1n, int lda1, int K1,
    const float* __restrict__ A2, long a2n, int lda2, int K2,
    const float* __restrict__ W1, const float* __restrict__ W1b, long w1n,
    const float* __restrict__ W2, long w2n,
    const float* __restrict__ bias, const float* __restrict__ biasb, long bn,
    float* __restrict__ C, float* __restrict__ Cb, long cn, int ldc, int O, int nodes)
{
    __shared__ uint32 AsH[2 * ASZ];
    __shared__ uint32 AsL[2 * ASZ];
    __shared__ uint32 BsH[2 * BSZ];
    __shared__ uint32 BsL[2 * BSZ];

    int z = blockIdx.z, node = z;
    const float* w1 = W1; const float* bsrc = bias; float* c = C;
    if (z >= nodes) { node = z - nodes; w1 = W1b; bsrc = biasb; c = Cb; }

    const int t = threadIdx.x;
    const int w = t >> 5, lane = t & 31;
    const int wm = w >> 2, wn = w & 3;
    const int g = lane >> 2, tg = lane & 3;
    const int row0 = blockIdx.y * 128;
    const int col0 = blockIdx.x * 128;

    float acc[4][4][4];
    #pragma unroll
    for (int i = 0; i < 4; i++)
        #pragma unroll
        for (int j = 0; j < 4; j++)
            #pragma unroll
            for (int r = 0; r < 4; r++) acc[i][j][r] = 0.f;

    bf_phase(A1 + (long)node * a1n, lda1, K1, w1 + (long)node * w1n, O, col0,
             row0, t, AsH, AsL, BsH, BsL, acc, wm, wn, g, tg);
    if (K2 > 0)
        bf_phase(A2 + (long)node * a2n, lda2, K2, W2 + (long)node * w2n, O, col0,
                 row0, t, AsH, AsL, BsH, BsL, acc, wm, wn, g, tg);

    const float* bp = bsrc + (long)node * bn;
    float* cbase = c + (long)node * cn;
    #pragma unroll
    for (int j = 0; j < 4; j++) {
        int col = col0 + wn * 32 + j * 8 + tg * 2;
        float2 bv = *(const float2*)&bp[col];
        #pragma unroll
        for (int i = 0; i < 4; i++) {
            int r = row0 + wm * 64 + i * 16 + g;
            float2 v0 = make_float2(acc[i][j][0] + bv.x, acc[i][j][1] + bv.y);
            float2 v1 = make_float2(acc[i][j][2] + bv.x, acc[i][j][3] + bv.y);
            *(float2*)&cbase[(long)r * ldc + col] = v0;
            *(float2*)&cbase[(long)(r + 8) * ldc + col] = v1;
        }
    }
}

// ---------------- fast G-mix + LSTM pointwise ----------------
// grid (2, 512): blockIdx.x = oc-half (64 ch), blockIdx.y = b. 256 threads.
__global__ __launch_bounds__(256) void k_mix_lstm_f(
    const float* __restrict__ gp, const float* __restrict__ G,
    float* __restrict__ h, float* __restrict__ c, float* __restrict__ yi)
{
    __shared__ float sg[NN * 256];   // [n][gate*64 + ocl]
    __shared__ float sG[NN * NN];
    const int och = blockIdx.x, b = blockIdx.y;
    const int t = threadIdx.x;
    const float* src = gp + (long)b * NN * G4;
    for (int e4 = t; e4 < NN * 256 / 4; e4 += 256) {
        int e = e4 * 4;
        int n = e >> 8, col = e & 255, g = col >> 6, j = col & 63;
        *(float4*)&sg[e] = *(const float4*)&src[n * G4 + g * 128 + och * 64 + j];
    }
    for (int e = t; e < NN * NN; e += 256) sG[e] = G[e];
    __syncthreads();

    const int ocl = t & 63;
    const int m0 = (t >> 6) * 6;
    float acc[6][4];
    #pragma unroll
    for (int j = 0; j < 6; j++)
        #pragma unroll
        for (int g = 0; g < 4; g++) acc[j][g] = 0.f;
    for (int n = 0; n < NN; n++) {
        float gv0 = sg[n * 256 + ocl];
        float gv1 = sg[n * 256 + 64 + ocl];
        float gv2 = sg[n * 256 + 128 + ocl];
        float gv3 = sg[n * 256 + 192 + ocl];
        #pragma unroll
        for (int j = 0; j < 6; j++) {
            float w = sG[(m0 + j) * NN + n];
            acc[j][0] += w * gv0; acc[j][1] += w * gv1;
            acc[j][2] += w * gv2; acc[j][3] += w * gv3;
        }
    }
    const int oc = och * 64 + ocl;
    #pragma unroll
    for (int j = 0; j < 6; j++) {
        long idx = ((long)b * NN + m0 + j) * OUTF + oc;
        float cc = sigf(acc[j][1]) * c[idx] + sigf(acc[j][0]) * tanhf(acc[j][2]);
        float hh = sigf(acc[j][3]) * tanhf(cc);
        c[idx] = cc;
        h[idx] = hh;
        if (yi) yi[idx] = tanhf(hh);
    }
}

// ---------------- fast G-mix + tanh for fc branches ----------------
__global__ __launch_bounds__(256) void k_mix_tanh2_f(
    const float* __restrict__ p1, const float* __restrict__ p2,
    const float* __restrict__ G,
    float* __restrict__ o1, float* __restrict__ o2)
{
    __shared__ float s1[NN * OUTF];
    __shared__ float s2[NN * OUTF];
    __shared__ float sG[NN * NN];
    const int b = blockIdx.x;
    const int t = threadIdx.x;
    const float* q1 = p1 + (long)b * NN * OUTF;
    const float* q2 = p2 + (long)b * NN * OUTF;
    for (int e4 = t; e4 < NN * OUTF / 4; e4 += 256) {
        *(float4*)&s1[e4 * 4] = *(const float4*)&q1[e4 * 4];
        *(float4*)&s2[e4 * 4] = *(const float4*)&q2[e4 * 4];
    }
    for (int e = t; e < NN * NN; e += 256) sG[e] = G[e];
    __syncthreads();

    const int ocl = t & 127;
    const int m0 = (t >> 7) * 12;
    #pragma unroll
    for (int mg = 0; mg < 3; mg++) {
        float a1[4] = {0.f, 0.f, 0.f, 0.f};
        float a2[4] = {0.f, 0.f, 0.f, 0.f};
        int mb = m0 + mg * 4;
        for (int n = 0; n < NN; n++) {
            float v1 = s1[n * OUTF + ocl];
            float v2 = s2[n * OUTF + ocl];
            #pragma unroll
            for (int j = 0; j < 4; j++) {
                float w = sG[(mb + j) * NN + n];
                a1[j] += w * v1; a2[j] += w * v2;
            }
        }
        #pragma unroll
        for (int j = 0; j < 4; j++) {
            long idx = ((long)b * NN + mb + j) * OUTF + ocl;
            o1[idx] = tanhf(a1[j]);
            o2[idx] = tanhf(a2[j]);
        }
    }
}

// ---------------- fast init mix: h0/c0 into both LSTM states ----------------
__global__ __launch_bounds__(256) void k_mix_init_f(
    const float* __restrict__ p1, const float* __restrict__ p2,
    const float* __restrict__ G)
{
    __shared__ float s1[NN * OUTF];
    __shared__ float s2[NN * OUTF];
    __shared__ float sG[NN * NN];
    const int b = blockIdx.x;
    const int t = threadIdx.x;
    const float* q1 = p1 + (long)b * NN * OUTF;
    const float* q2 = p2 + (long)b * NN * OUTF;
    for (int e4 = t; e4 < NN * OUTF / 4; e4 += 256) {
        *(float4*)&s1[e4 * 4] = *(const float4*)&q1[e4 * 4];
        *(float4*)&s2[e4 * 4] = *(const float4*)&q2[e4 * 4];
    }
    for (int e = t; e < NN * NN; e += 256) sG[e] = G[e];
    __syncthreads();

    const int ocl = t & 127;
    const int m0 = (t >> 7) * 12;
    #pragma unroll
    for (int mg = 0; mg < 3; mg++) {
        float a1[4] = {0.f, 0.f, 0.f, 0.f};
        float a2[4] = {0.f, 0.f, 0.f, 0.f};
        int mb = m0 + mg * 4;
        for (int n = 0; n < NN; n++) {
            float v1 = s1[n * OUTF + ocl];
            float v2 = s2[n * OUTF + ocl];
            #pragma unroll
            for (int j = 0; j < 4; j++) {
                float w = sG[(mb + j) * NN + n];
                a1[j] += w * v1; a2[j] += w * v2;
            }
        }
        #pragma unroll
        for (int j = 0; j < 4; j++) {
            long idx = ((long)b * NN + mb + j) * OUTF + ocl;
            g_h1[idx] = a1[j]; g_h2[idx] = a1[j];
            g_c1[idx] = a2[j]; g_c2[idx] = a2[j];
        }
    }
}

// ---------------- init xi / loc_start ----------------
__global__ void k_init_xi(const float* __restrict__ x, const float* __restrict__ z)
{
    int idx = blockIdx.x * blockDim.x + threadIdx.x;
    if (idx >= BB * NN * XIF) return;
    int j = idx % XIF;
    int bn = idx / XIF;
    float v;
    if (j < LL) {
        v = z[(long)bn * LL + j];
    } else {
        v = x[(long)bn * IN_F + (j - LL)];
        if (j < LL + 4) g_ls[(long)bn * 4 + (j - LL)] = v;
    }
    g_xi[idx] = v;
}

// ---------------- per-(b,n) head pre-projection: [3 loc | 4 logz] ----------------
__global__ __launch_bounds__(128) void k_head_pre(
    const float* __restrict__ locW, const float* __restrict__ logzW)
{
    int w = blockIdx.x * 4 + (threadIdx.x >> 5);
    int lane = threadIdx.x & 31;
    long base = (long)w * OUTF + lane * 4;
    float4 v1 = *reinterpret_cast<const float4*>(&g_yi1[base]);
    float4 v2 = *reinterpret_cast<const float4*>(&g_yi2[base]);
    float a[7] = {0.f, 0.f, 0.f, 0.f, 0.f, 0.f, 0.f};
    float x1[4] = {v1.x, v1.y, v1.z, v1.w};
    float x2[4] = {v2.x, v2.y, v2.z, v2.w};
    #pragma unroll
    for (int j = 0; j < 4; j++) {
        int f = lane * 4 + j;
        a[0] += x1[j] * locW[f * 3 + 0];
        a[1] += x1[j] * locW[f * 3 + 1];
        a[2] += x1[j] * locW[f * 3 + 2];
        a[3] += x2[j] * logzW[f * 4 + 0];
        a[4] += x2[j] * logzW[f * 4 + 1];
        a[5] += x2[j] * logzW[f * 4 + 2];
        a[6] += x2[j] * logzW[f * 4 + 3];
    }
    #pragma unroll
    for (int s = 16; s > 0; s >>= 1)
        #pragma unroll
        for (int k = 0; k < 7; k++)
            a[k] += __shfl_xor_sync(0xFFFFFFFFu, a[k], s);
    if (lane == 0) {
        #pragma unroll
        for (int k = 0; k < 7; k++) g_hp[(long)w * 8 + k] = a[k];
    }
}

// ---------------- final: G-mix head, normalize, quat-mul, outputs, next xi ----------------
__global__ __launch_bounds__(64) void k_final(
    const float* __restrict__ G,
    const float* __restrict__ locb, const float* __restrict__ logzb,
    float* __restrict__ out, int t)
{
    const int b = blockIdx.x;
    const int tid = threadIdx.x;
    __shared__ float hps[NN][8];
    for (int e = tid; e < NN * 8; e += 64)
        (&hps[0][0])[e] = g_hp[(long)b * NN * 8 + e];
    __syncthreads();
    if (tid < NN) {
        const int m = tid;
        float l0 = locb[0], l1 = locb[1], l2 = locb[2];
        float z0 = logzb[0], z1 = logzb[1], z2 = logzb[2], z3 = logzb[3];
        #pragma unroll 4
        for (int n = 0; n < NN; n++) {
            float w = G[m * NN + n];
            l0 += w * hps[n][0]; l1 += w * hps[n][1]; l2 += w * hps[n][2];
            z0 += w * hps[n][3]; z1 += w * hps[n][4];
            z2 += w * hps[n][5]; z3 += w * hps[n][6];
        }
        float r = rsqrtf(1.0f + l0 * l0 + l1 * l1 + l2 * l2);
        float d0 = r, d1 = l0 * r, d2 = l1 * r, d3 = l2 * r;
        float* ls = &g_ls[((long)b * NN + m) * 4];
        float w1 = ls[0], x1 = ls[1], y1 = ls[2], zz1 = ls[3];
        float q0 = w1 * d0 - x1 * d1 - y1 * d2 - zz1 * d3;
        float q1 = w1 * d1 + x1 * d0 + y1 * d3 - zz1 * d2;
        float q2 = w1 * d2 - x1 * d3 + y1 * d0 + zz1 * d1;
        float q3 = w1 * d3 + x1 * d2 - y1 * d1 + zz1 * d0;
        ls[0] = q0; ls[1] = q1; ls[2] = q2; ls[3] = q3;
        long ob = (((long)b * TT + t) * NN + m) * 4;
        out[ob + 0] = q0; out[ob + 1] = q1; out[ob + 2] = q2; out[ob + 3] = q3;
        const long ZOFF = (long)BB * TT * NN * 4;
        out[ZOFF + ob + 0] = z0; out[ZOFF + ob + 1] = z1;
        out[ZOFF + ob + 2] = z2; out[ZOFF + ob + 3] = z3;
        float* xr = &g_xi[((long)b * NN + m) * XIF];
        xr[64] = q0; xr[65] = q1; xr[66] = q2; xr[67] = q3;
        xr[68] = d0; xr[69] = d1; xr[70] = d2; xr[71] = d3;
    }
}

// ---------------- host ----------------
extern "C" void kernel_launch(void* const* d_in, const int* in_sizes, int n_in,
                              void* d_out, int out_size)
{
    const float* x     = (const float*)d_in[0];
    const float* enc   = (const float*)d_in[1];
    const float* z     = (const float*)d_in[2];
    /* d_in[3] = y, unused by the reference */
    const float* G     = (const float*)d_in[4];
    const float* Wx0   = (const float*)d_in[5];
    const float* Wh0   = (const float*)d_in[6];
    const float* b0    = (const float*)d_in[7];
    const float* Wx1   = (const float*)d_in[8];
    const float* Wh1   = (const float*)d_in[9];
    const float* b1    = (const float*)d_in[10];
    const float* fcW   = (const float*)d_in[11];
    const float* fcb   = (const float*)d_in[12];
    const float* fc2W  = (const float*)d_in[13];
    const float* fc2b  = (const float*)d_in[14];
    const float* ih1W  = (const float*)d_in[15];
    const float* ih1b  = (const float*)d_in[16];
    const float* ih2W  = (const float*)d_in[17];
    const float* ih2b  = (const float*)d_in[18];
    const float* locW  = (const float*)d_in[19];
    const float* locb  = (const float*)d_in[20];
    const float* logzW = (const float*)d_in[21];
    const float* logzb = (const float*)d_in[22];
    float* out = (float*)d_out;

    float *xi, *h1, *c1, *h2, *c2, *gts, *p1, *p2, *yi, *yi1, *yi2;
    cudaGetSymbolAddress((void**)&xi,  g_xi);
    cudaGetSymbolAddress((void**)&h1,  g_h1);
    cudaGetSymbolAddress((void**)&c1,  g_c1);
    cudaGetSymbolAddress((void**)&h2,  g_h2);
    cudaGetSymbolAddress((void**)&c2,  g_c2);
    cudaGetSymbolAddress((void**)&gts, g_gts);
    cudaGetSymbolAddress((void**)&p1,  g_p1);
    cudaGetSymbolAddress((void**)&p2,  g_p2);
    cudaGetSymbolAddress((void**)&yi,  g_yi);
    cudaGetSymbolAddress((void**)&yi1, g_yi1);
    cudaGetSymbolAddress((void**)&yi2, g_yi2);

    // ---- init ----
    {
        int tot = BB * NN * XIF;
        k_init_xi<<<(tot + 255) / 256, 256>>>(x, z);
    }
    // fused: enc @ ih1_W -> p1 (z=0) and enc @ ih2_W -> p2 (z=1)
    {
        dim3 grid(1, (BB * NN) / 128, 2);
        gemm_bf<<<grid, 256>>>(enc, 0, HH, HH,
                               enc, 0, HH, 0,
                               ih1W, ih2W, 0,
                               ih1W, 0,
                               ih1b, ih2b, 0,
                               p1, p2, 0, OUTF, OUTF, 1);
    }
    k_mix_init_f<<<BB, 256>>>(p1, p2, G);

    // ---- T sequential steps ----
    for (int t = 0; t < TT; t++) {
        // LSTM1 gates: xi @ Wx0[n] + h1 @ Wh0[n] + b0[n]
        {
            dim3 grid(G4 / 128, BB / 128, NN);
            gemm_bf<<<grid, 256>>>(xi, XIF, NN * XIF, XIF,
                                   h1, OUTF, NN * OUTF, OUTF,
                                   Wx0, Wx0, (long)XIF * G4,
                                   Wh0, (long)OUTF * G4,
                                   b0, b0, G4,
                                   gts, gts, G4, NN * G4, G4, NN);
        }
        { dim3 grid(2, BB); k_mix_lstm_f<<<grid, 256>>>(gts, G, h1, c1, nullptr); }
        // LSTM2 gates: h1 @ Wx1[n] + h2 @ Wh1[n] + b1[n]
        {
            dim3 grid(G4 / 128, BB / 128, NN);
            gemm_bf<<<grid, 256>>>(h1, OUTF, NN * OUTF, OUTF,
                                   h2, OUTF, NN * OUTF, OUTF,
                                   Wx1, Wx1, (long)OUTF * G4,
                                   Wh1, (long)OUTF * G4,
                                   b1, b1, G4,
                                   gts, gts, G4, NN * G4, G4, NN);
        }
        { dim3 grid(2, BB); k_mix_lstm_f<<<grid, 256>>>(gts, G, h2, c2, yi); }
        // fused fc / fc2: yi @ fc_W[n] -> p1 (z<24), yi @ fc2_W[n] -> p2 (z>=24)
        {
            dim3 grid(1, BB / 128, 2 * NN);
            gemm_bf<<<grid, 256>>>(yi, OUTF, NN * OUTF, OUTF,
                                   yi, OUTF, NN * OUTF, 0,
                                   fcW, fc2W, (long)OUTF * OUTF,
                                   fcW, 0,
                                   fcb, fc2b, OUTF,
                                   p1, p2, OUTF, NN * OUTF, OUTF, NN);
        }
        k_mix_tanh2_f<<<BB, 256>>>(p1, p2, G, yi1, yi2);
        // head projections + finalize
        k_head_pre<<<(BB * NN) / 4, 128>>>(locW, logzW);
        k_final<<<BB, 64>>>(G, locb, logzb, out, t);
    }
}

// round 8
// speedup vs baseline: 3.1438x; 1.0965x over previous
#include <cuda_runtime.h>
#include <cuda_bf16.h>
#include <math.h>

#define BB 512
#define NN 24
#define TT 25
#define IN_F 8
#define LL 64
#define HH 256
#define OUTF 128
#define XIF 72
#define G4 512

typedef unsigned int uint32;

// ---------------- scratch (device globals; allocation-free) ----------------
__device__ float g_xi [BB*NN*XIF];
__device__ float g_h1 [BB*NN*OUTF];
__device__ float g_c1 [BB*NN*OUTF];
__device__ float g_h2 [BB*NN*OUTF];
__device__ float g_c2 [BB*NN*OUTF];
__device__ float g_gts[BB*NN*G4];
__device__ float g_p1 [BB*NN*OUTF];
__device__ float g_p2 [BB*NN*OUTF];
__device__ float g_yi [BB*NN*OUTF];
__device__ float g_ls [BB*NN*4];

__device__ __forceinline__ float sigf(float v) { return 1.0f / (1.0f + expf(-v)); }

// split a pair of floats (consecutive k) into packed bf16 hi and lo words
__device__ __forceinline__ void splitpair(float a, float b, uint32& h, uint32& l) {
    __nv_bfloat16 ha = __float2bfloat16_rn(a);
    __nv_bfloat16 hb = __float2bfloat16_rn(b);
    float ra = a - __bfloat162float(ha);
    float rb = b - __bfloat162float(hb);
    __nv_bfloat162 hh; hh.x = ha; hh.y = hb;
    __nv_bfloat162 ll; ll.x = __float2bfloat16_rn(ra); ll.y = __float2bfloat16_rn(rb);
    h = *reinterpret_cast<uint32*>(&hh);
    l = *reinterpret_cast<uint32*>(&ll);
}

__device__ __forceinline__ void mma_bf16(
    float& d0, float& d1, float& d2, float& d3,
    uint32 a0, uint32 a1, uint32 a2, uint32 a3, uint32 b0, uint32 b1)
{
    asm volatile(
        "mma.sync.aligned.m16n8k16.row.col.f32.bf16.bf16.f32 "
        "{%0,%1,%2,%3}, {%4,%5,%6,%7}, {%8,%9}, {%0,%1,%2,%3};"
        : "+f"(d0), "+f"(d1), "+f"(d2), "+f"(d3)
        : "r"(a0), "r"(a1), "r"(a2), "r"(a3), "r"(b0), "r"(b1));
}

// ---------------- bf16x2-split tensor-core GEMM ----------------
#define KC 16
#define AP 12
#define BP 136
#define ASZ (128 * AP)
#define BSZ (8 * BP)

__device__ __forceinline__ void bf_phase(
    const float* __restrict__ A, int lda, int K,
    const float* __restrict__ W, int ldw, int col0, int row0,
    int t, uint32* AsH, uint32* AsL, uint32* BsH, uint32* BsL,
    float (&acc)[4][4][4], int wm, int wn, int g, int tg)
{
    const int nch = (K + KC - 1) / KC;
    const int arow = t >> 1, akp0 = (t & 1) * 4;
    const int bkp = t >> 5, bn = (t & 31) * 4;
    const float4 z4 = make_float4(0.f, 0.f, 0.f, 0.f);
    float4 a0, a1, b0, b1;

    const float* aptr = &A[(long)(row0 + arow) * lda + akp0 * 2];
    const float* bptr = &W[(long)(2 * bkp) * ldw + col0 + bn];
    int ka = akp0 * 2;
    int kb = 2 * bkp;

    {
        bool va = (ka < K);
        a0 = va ? *(const float4*)aptr : z4;
        a1 = va ? *(const float4*)(aptr + 4) : z4;
        bool vb = (kb < K);
        b0 = vb ? *(const float4*)bptr : z4;
        b1 = vb ? *(const float4*)(bptr + ldw) : z4;
    }
    {
        uint4 h, l;
        splitpair(a0.x, a0.y, h.x, l.x); splitpair(a0.z, a0.w, h.y, l.y);
        splitpair(a1.x, a1.y, h.z, l.z); splitpair(a1.z, a1.w, h.w, l.w);
        *(uint4*)&AsH[arow * AP + akp0] = h;
        *(uint4*)&AsL[arow * AP + akp0] = l;
        splitpair(b0.x, b1.x, h.x, l.x); splitpair(b0.y, b1.y, h.y, l.y);
        splitpair(b0.z, b1.z, h.z, l.z); splitpair(b0.w, b1.w, h.w, l.w);
        *(uint4*)&BsH[bkp * BP + bn] = h;
        *(uint4*)&BsL[bkp * BP + bn] = l;
    }
    __syncthreads();

    for (int c = 0; c < nch; c++) {
        const int buf = c & 1;
        uint32* ah_s = AsH + buf * ASZ;
        uint32* al_s = AsL + buf * ASZ;
        uint32* bh_s = BsH + buf * BSZ;
        uint32* bl_s = BsL + buf * BSZ;

        if (c + 1 < nch) {
            aptr += KC;
            bptr += (long)KC * ldw;
            ka += KC;
            kb += KC;
            bool va = (ka < K);
            a0 = va ? *(const float4*)aptr : z4;
            a1 = va ? *(const float4*)(aptr + 4) : z4;
            bool vb = (kb < K);
            b0 = vb ? *(const float4*)bptr : z4;
            b1 = vb ? *(const float4*)(bptr + ldw) : z4;
        }

        uint32 ah[4][4], al[4][4];
        #pragma unroll
        for (int i = 0; i < 4; i++) {
            int base = (wm * 64 + i * 16 + g) * AP;
            ah[i][0] = ah_s[base + tg];
            ah[i][1] = ah_s[base + 8 * AP + tg];
            ah[i][2] = ah_s[base + tg + 4];
            ah[i][3] = ah_s[base + 8 * AP + tg + 4];
            al[i][0] = al_s[base + tg];
            al[i][1] = al_s[base + 8 * AP + tg];
            al[i][2] = al_s[base + tg + 4];
            al[i][3] = al_s[base + 8 * AP + tg + 4];
        }
        #pragma unroll
        for (int j = 0; j < 4; j++) {
            int nc = wn * 32 + j * 8 + g;
            uint32 bh0 = bh_s[tg * BP + nc];
            uint32 bh1 = bh_s[(tg + 4) * BP + nc];
            uint32 bl0 = bl_s[tg * BP + nc];
            uint32 bl1 = bl_s[(tg + 4) * BP + nc];
            #pragma unroll
            for (int i = 0; i < 4; i++) {
                mma_bf16(acc[i][j][0], acc[i][j][1], acc[i][j][2], acc[i][j][3],
                         ah[i][0], ah[i][1], ah[i][2], ah[i][3], bh0, bh1);
                mma_bf16(acc[i][j][0], acc[i][j][1], acc[i][j][2], acc[i][j][3],
                         ah[i][0], ah[i][1], ah[i][2], ah[i][3], bl0, bl1);
                mma_bf16(acc[i][j][0], acc[i][j][1], acc[i][j][2], acc[i][j][3],
                         al[i][0], al[i][1], al[i][2], al[i][3], bh0, bh1);
            }
        }

        if (c + 1 < nch) {
            uint32* nah = AsH + (1 - buf) * ASZ;
            uint32* nal = AsL + (1 - buf) * ASZ;
            uint32* nbh = BsH + (1 - buf) * BSZ;
            uint32* nbl = BsL + (1 - buf) * BSZ;
            uint4 h, l;
            splitpair(a0.x, a0.y, h.x, l.x); splitpair(a0.z, a0.w, h.y, l.y);
            splitpair(a1.x, a1.y, h.z, l.z); splitpair(a1.z, a1.w, h.w, l.w);
            *(uint4*)&nah[arow * AP + akp0] = h;
            *(uint4*)&nal[arow * AP + akp0] = l;
            splitpair(b0.x, b1.x, h.x, l.x); splitpair(b0.y, b1.y, h.y, l.y);
            splitpair(b0.z, b1.z, h.z, l.z); splitpair(b0.w, b1.w, h.w, l.w);
            *(uint4*)&nbh[bkp * BP + bn] = h;
            *(uint4*)&nbl[bkp * BP + bn] = l;
            __syncthreads();
        }
    }
    __syncthreads();
}

// C[node] = A1[node] @ W1[node] (+ A2[node] @ W2[node]) + bias[node]
__global__ __launch_bounds__(256) void gemm_bf(
    const float* __restrict__ A1, long a1n, int lda1, int K1,
    const float* __restrict__ A2, long a2n, int lda2, int K2,
    const float* __restrict__ W1, const float* __restrict__ W1b, long w1n,
    const float* __restrict__ W2, long w2n,
    const float* __restrict__ bias, const float* __restrict__ biasb, long bn,
    float* __restrict__ C, float* __restrict__ Cb, long cn, int ldc, int O, int nodes)
{
    __shared__ uint32 AsH[2 * ASZ];
    __shared__ uint32 AsL[2 * ASZ];
    __shared__ uint32 BsH[2 * BSZ];
    __shared__ uint32 BsL[2 * BSZ];

    int z = blockIdx.z, node = z;
    const float* w1 = W1; const float* bsrc = bias; float* c = C;
    if (z >= nodes) { node = z - nodes; w1 = W1b; bsrc = biasb; c = Cb; }

    const int t = threadIdx.x;
    const int w = t >> 5, lane = t & 31;
    const int wm = w >> 2, wn = w & 3;
    const int g = lane >> 2, tg = lane & 3;
    const int row0 = blockIdx.y * 128;
    const int col0 = blockIdx.x * 128;

    float acc[4][4][4];
    #pragma unroll
    for (int i = 0; i < 4; i++)
        #pragma unroll
        for (int j = 0; j < 4; j++)
            #pragma unroll
            for (int r = 0; r < 4; r++) acc[i][j][r] = 0.f;

    bf_phase(A1 + (long)node * a1n, lda1, K1, w1 + (long)node * w1n, O, col0,
             row0, t, AsH, AsL, BsH, BsL, acc, wm, wn, g, tg);
    if (K2 > 0)
        bf_phase(A2 + (long)node * a2n, lda2, K2, W2 + (long)node * w2n, O, col0,
                 row0, t, AsH, AsL, BsH, BsL, acc, wm, wn, g, tg);

    const float* bp = bsrc + (long)node * bn;
    float* cbase = c + (long)node * cn;
    #pragma unroll
    for (int j = 0; j < 4; j++) {
        int col = col0 + wn * 32 + j * 8 + tg * 2;
        float2 bv = *(const float2*)&bp[col];
        #pragma unroll
        for (int i = 0; i < 4; i++) {
            int r = row0 + wm * 64 + i * 16 + g;
            float2 v0 = make_float2(acc[i][j][0] + bv.x, acc[i][j][1] + bv.y);
            float2 v1 = make_float2(acc[i][j][2] + bv.x, acc[i][j][3] + bv.y);
            *(float2*)&cbase[(long)r * ldc + col] = v0;
            *(float2*)&cbase[(long)(r + 8) * ldc + col] = v1;
        }
    }
}

// ---------------- fast G-mix + LSTM pointwise ----------------
// grid (2, 512): blockIdx.x = oc-half (64 ch), blockIdx.y = b. 256 threads.
__global__ __launch_bounds__(256) void k_mix_lstm_f(
    const float* __restrict__ gp, const float* __restrict__ G,
    float* __restrict__ h, float* __restrict__ c, float* __restrict__ yi)
{
    __shared__ float sg[NN * 256];   // [n][gate*64 + ocl]
    __shared__ float sG[NN * NN];
    const int och = blockIdx.x, b = blockIdx.y;
    const int t = threadIdx.x;
    const float* src = gp + (long)b * NN * G4;
    for (int e4 = t; e4 < NN * 256 / 4; e4 += 256) {
        int e = e4 * 4;
        int n = e >> 8, col = e & 255, g = col >> 6, j = col & 63;
        *(float4*)&sg[e] = *(const float4*)&src[n * G4 + g * 128 + och * 64 + j];
    }
    for (int e = t; e < NN * NN; e += 256) sG[e] = G[e];
    __syncthreads();

    const int ocl = t & 63;
    const int m0 = (t >> 6) * 6;
    float acc[6][4];
    #pragma unroll
    for (int j = 0; j < 6; j++)
        #pragma unroll
        for (int g = 0; g < 4; g++) acc[j][g] = 0.f;
    for (int n = 0; n < NN; n++) {
        float gv0 = sg[n * 256 + ocl];
        float gv1 = sg[n * 256 + 64 + ocl];
        float gv2 = sg[n * 256 + 128 + ocl];
        float gv3 = sg[n * 256 + 192 + ocl];
        #pragma unroll
        for (int j = 0; j < 6; j++) {
            float w = sG[(m0 + j) * NN + n];
            acc[j][0] += w * gv0; acc[j][1] += w * gv1;
            acc[j][2] += w * gv2; acc[j][3] += w * gv3;
        }
    }
    const int oc = och * 64 + ocl;
    #pragma unroll
    for (int j = 0; j < 6; j++) {
        long idx = ((long)b * NN + m0 + j) * OUTF + oc;
        float cc = sigf(acc[j][1]) * c[idx] + sigf(acc[j][0]) * tanhf(acc[j][2]);
        float hh = sigf(acc[j][3]) * tanhf(cc);
        c[idx] = cc;
        h[idx] = hh;
        if (yi) yi[idx] = tanhf(hh);
    }
}

// ---------------- fast init mix: h0/c0 into both LSTM states ----------------
__global__ __launch_bounds__(256) void k_mix_init_f(
    const float* __restrict__ p1, const float* __restrict__ p2,
    const float* __restrict__ G)
{
    __shared__ float s1[NN * OUTF];
    __shared__ float s2[NN * OUTF];
    __shared__ float sG[NN * NN];
    const int b = blockIdx.x;
    const int t = threadIdx.x;
    const float* q1 = p1 + (long)b * NN * OUTF;
    const float* q2 = p2 + (long)b * NN * OUTF;
    for (int e4 = t; e4 < NN * OUTF / 4; e4 += 256) {
        *(float4*)&s1[e4 * 4] = *(const float4*)&q1[e4 * 4];
        *(float4*)&s2[e4 * 4] = *(const float4*)&q2[e4 * 4];
    }
    for (int e = t; e < NN * NN; e += 256) sG[e] = G[e];
    __syncthreads();

    const int ocl = t & 127;
    const int m0 = (t >> 7) * 12;
    #pragma unroll
    for (int mg = 0; mg < 3; mg++) {
        float a1[4] = {0.f, 0.f, 0.f, 0.f};
        float a2[4] = {0.f, 0.f, 0.f, 0.f};
        int mb = m0 + mg * 4;
        for (int n = 0; n < NN; n++) {
            float v1 = s1[n * OUTF + ocl];
            float v2 = s2[n * OUTF + ocl];
            #pragma unroll
            for (int j = 0; j < 4; j++) {
                float w = sG[(mb + j) * NN + n];
                a1[j] += w * v1; a2[j] += w * v2;
            }
        }
        #pragma unroll
        for (int j = 0; j < 4; j++) {
            long idx = ((long)b * NN + mb + j) * OUTF + ocl;
            g_h1[idx] = a1[j]; g_h2[idx] = a1[j];
            g_c1[idx] = a2[j]; g_c2[idx] = a2[j];
        }
    }
}

// ---------------- init xi / loc_start ----------------
__global__ void k_init_xi(const float* __restrict__ x, const float* __restrict__ z)
{
    int idx = blockIdx.x * blockDim.x + threadIdx.x;
    if (idx >= BB * NN * XIF) return;
    int j = idx % XIF;
    int bn = idx / XIF;
    float v;
    if (j < LL) {
        v = z[(long)bn * LL + j];
    } else {
        v = x[(long)bn * IN_F + (j - LL)];
        if (j < LL + 4) g_ls[(long)bn * 4 + (j - LL)] = v;
    }
    g_xi[idx] = v;
}

// ---------------- fused tail: mix+tanh, head projections, final ----------------
// one block per b, 256 threads.
__global__ __launch_bounds__(256) void k_tail(
    const float* __restrict__ p1, const float* __restrict__ p2,
    const float* __restrict__ G,
    const float* __restrict__ locW, const float* __restrict__ locb,
    const float* __restrict__ logzW, const float* __restrict__ logzb,
    float* __restrict__ out, int t)
{
    __shared__ float s1[NN * OUTF];
    __shared__ float s2[NN * OUTF];
    __shared__ float sG[NN * NN];
    __shared__ float hp[NN][8];
    const int b = blockIdx.x;
    const int tid = threadIdx.x;
    const float* q1 = p1 + (long)b * NN * OUTF;
    const float* q2 = p2 + (long)b * NN * OUTF;
    for (int e4 = tid; e4 < NN * OUTF / 4; e4 += 256) {
        *(float4*)&s1[e4 * 4] = *(const float4*)&q1[e4 * 4];
        *(float4*)&s2[e4 * 4] = *(const float4*)&q2[e4 * 4];
    }
    for (int e = tid; e < NN * NN; e += 256) sG[e] = G[e];
    __syncthreads();

    // --- stage 1: G-mix + tanh into registers ---
    const int ocl = tid & 127;
    const int m0 = (tid >> 7) * 12;
    float r1[12], r2[12];
    #pragma unroll
    for (int mg = 0; mg < 3; mg++) {
        float a1[4] = {0.f, 0.f, 0.f, 0.f};
        float a2[4] = {0.f, 0.f, 0.f, 0.f};
        int mb = m0 + mg * 4;
        for (int n = 0; n < NN; n++) {
            float v1 = s1[n * OUTF + ocl];
            float v2 = s2[n * OUTF + ocl];
            #pragma unroll
            for (int j = 0; j < 4; j++) {
                float w = sG[(mb + j) * NN + n];
                a1[j] += w * v1; a2[j] += w * v2;
            }
        }
        #pragma unroll
        for (int j = 0; j < 4; j++) {
            r1[mg * 4 + j] = tanhf(a1[j]);
            r2[mg * 4 + j] = tanhf(a2[j]);
        }
    }
    __syncthreads();
    // overwrite s1/s2 with yi1/yi2
    #pragma unroll
    for (int k = 0; k < 12; k++) {
        s1[(m0 + k) * OUTF + ocl] = r1[k];
        s2[(m0 + k) * OUTF + ocl] = r2[k];
    }
    __syncthreads();

    // --- stage 2: head projections (warp w handles m = w*3..w*3+2) ---
    const int wid = tid >> 5, lane = tid & 31;
    #pragma unroll
    for (int mm = 0; mm < 3; mm++) {
        int m = wid * 3 + mm;
        float4 v1 = *(const float4*)&s1[m * OUTF + lane * 4];
        float4 v2 = *(const float4*)&s2[m * OUTF + lane * 4];
        float a[7] = {0.f, 0.f, 0.f, 0.f, 0.f, 0.f, 0.f};
        float x1[4] = {v1.x, v1.y, v1.z, v1.w};
        float x2[4] = {v2.x, v2.y, v2.z, v2.w};
        #pragma unroll
        for (int j = 0; j < 4; j++) {
            int f = lane * 4 + j;
            a[0] += x1[j] * locW[f * 3 + 0];
            a[1] += x1[j] * locW[f * 3 + 1];
            a[2] += x1[j] * locW[f * 3 + 2];
            a[3] += x2[j] * logzW[f * 4 + 0];
            a[4] += x2[j] * logzW[f * 4 + 1];
            a[5] += x2[j] * logzW[f * 4 + 2];
            a[6] += x2[j] * logzW[f * 4 + 3];
        }
        #pragma unroll
        for (int s = 16; s > 0; s >>= 1)
            #pragma unroll
            for (int k = 0; k < 7; k++)
                a[k] += __shfl_xor_sync(0xFFFFFFFFu, a[k], s);
        if (lane == 0) {
            #pragma unroll
            for (int k = 0; k < 7; k++) hp[m][k] = a[k];
        }
    }
    __syncthreads();

    // --- stage 3: final (G-mix of heads, normalize, quat, outputs) ---
    if (tid < NN) {
        const int m = tid;
        float l0 = locb[0], l1 = locb[1], l2 = locb[2];
        float z0 = logzb[0], z1 = logzb[1], z2 = logzb[2], z3 = logzb[3];
        #pragma unroll 4
        for (int n = 0; n < NN; n++) {
            float w = sG[m * NN + n];
            l0 += w * hp[n][0]; l1 += w * hp[n][1]; l2 += w * hp[n][2];
            z0 += w * hp[n][3]; z1 += w * hp[n][4];
            z2 += w * hp[n][5]; z3 += w * hp[n][6];
        }
        float r = rsqrtf(1.0f + l0 * l0 + l1 * l1 + l2 * l2);
        float d0 = r, d1 = l0 * r, d2 = l1 * r, d3 = l2 * r;
        float* ls = &g_ls[((long)b * NN + m) * 4];
        float w1 = ls[0], x1 = ls[1], y1 = ls[2], zz1 = ls[3];
        float q0 = w1 * d0 - x1 * d1 - y1 * d2 - zz1 * d3;
        float q1 = w1 * d1 + x1 * d0 + y1 * d3 - zz1 * d2;
        float q2 = w1 * d2 - x1 * d3 + y1 * d0 + zz1 * d1;
        float q3 = w1 * d3 + x1 * d2 - y1 * d1 + zz1 * d0;
        ls[0] = q0; ls[1] = q1; ls[2] = q2; ls[3] = q3;
        long ob = (((long)b * TT + t) * NN + m) * 4;
        out[ob + 0] = q0; out[ob + 1] = q1; out[ob + 2] = q2; out[ob + 3] = q3;
        const long ZOFF = (long)BB * TT * NN * 4;
        out[ZOFF + ob + 0] = z0; out[ZOFF + ob + 1] = z1;
        out[ZOFF + ob + 2] = z2; out[ZOFF + ob + 3] = z3;
        float* xr = &g_xi[((long)b * NN + m) * XIF];
        xr[64] = q0; xr[65] = q1; xr[66] = q2; xr[67] = q3;
        xr[68] = d0; xr[69] = d1; xr[70] = d2; xr[71] = d3;
    }
}

// ---------------- host ----------------
extern "C" void kernel_launch(void* const* d_in, const int* in_sizes, int n_in,
                              void* d_out, int out_size)
{
    const float* x     = (const float*)d_in[0];
    const float* enc   = (const float*)d_in[1];
    const float* z     = (const float*)d_in[2];
    /* d_in[3] = y, unused by the reference */
    const float* G     = (const float*)d_in[4];
    const float* Wx0   = (const float*)d_in[5];
    const float* Wh0   = (const float*)d_in[6];
    const float* b0    = (const float*)d_in[7];
    const float* Wx1   = (const float*)d_in[8];
    const float* Wh1   = (const float*)d_in[9];
    const float* b1    = (const float*)d_in[10];
    const float* fcW   = (const float*)d_in[11];
    const float* fcb   = (const float*)d_in[12];
    const float* fc2W  = (const float*)d_in[13];
    const float* fc2b  = (const float*)d_in[14];
    const float* ih1W  = (const float*)d_in[15];
    const float* ih1b  = (const float*)d_in[16];
    const float* ih2W  = (const float*)d_in[17];
    const float* ih2b  = (const float*)d_in[18];
    const float* locW  = (const float*)d_in[19];
    const float* locb  = (const float*)d_in[20];
    const float* logzW = (const float*)d_in[21];
    const float* logzb = (const float*)d_in[22];
    float* out = (float*)d_out;

    float *xi, *h1, *c1, *h2, *c2, *gts, *p1, *p2, *yi;
    cudaGetSymbolAddress((void**)&xi,  g_xi);
    cudaGetSymbolAddress((void**)&h1,  g_h1);
    cudaGetSymbolAddress((void**)&c1,  g_c1);
    cudaGetSymbolAddress((void**)&h2,  g_h2);
    cudaGetSymbolAddress((void**)&c2,  g_c2);
    cudaGetSymbolAddress((void**)&gts, g_gts);
    cudaGetSymbolAddress((void**)&p1,  g_p1);
    cudaGetSymbolAddress((void**)&p2,  g_p2);
    cudaGetSymbolAddress((void**)&yi,  g_yi);

    // ---- init ----
    {
        int tot = BB * NN * XIF;
        k_init_xi<<<(tot + 255) / 256, 256>>>(x, z);
    }
    // fused: enc @ ih1_W -> p1 (z=0) and enc @ ih2_W -> p2 (z=1)
    {
        dim3 grid(1, (BB * NN) / 128, 2);
        gemm_bf<<<grid, 256>>>(enc, 0, HH, HH,
                               enc, 0, HH, 0,
                               ih1W, ih2W, 0,
                               ih1W, 0,
                               ih1b, ih2b, 0,
                               p1, p2, 0, OUTF, OUTF, 1);
    }
    k_mix_init_f<<<BB, 256>>>(p1, p2, G);

    // ---- T sequential steps ----
    for (int t = 0; t < TT; t++) {
        // LSTM1 gates: xi @ Wx0[n] + h1 @ Wh0[n] + b0[n]
        {
            dim3 grid(G4 / 128, BB / 128, NN);
            gemm_bf<<<grid, 256>>>(xi, XIF, NN * XIF, XIF,
                                   h1, OUTF, NN * OUTF, OUTF,
                                   Wx0, Wx0, (long)XIF * G4,
                                   Wh0, (long)OUTF * G4,
                                   b0, b0, G4,
                                   gts, gts, G4, NN * G4, G4, NN);
        }
        { dim3 grid(2, BB); k_mix_lstm_f<<<grid, 256>>>(gts, G, h1, c1, nullptr); }
        // LSTM2 gates: h1 @ Wx1[n] + h2 @ Wh1[n] + b1[n]
        {
            dim3 grid(G4 / 128, BB / 128, NN);
            gemm_bf<<<grid, 256>>>(h1, OUTF, NN * OUTF, OUTF,
                                   h2, OUTF, NN * OUTF, OUTF,
                                   Wx1, Wx1, (long)OUTF * G4,
                                   Wh1, (long)OUTF * G4,
                                   b1, b1, G4,
                                   gts, gts, G4, NN * G4, G4, NN);
        }
        { dim3 grid(2, BB); k_mix_lstm_f<<<grid, 256>>>(gts, G, h2, c2, yi); }
        // fused fc / fc2: yi @ fc_W[n] -> p1 (z<24), yi @ fc2_W[n] -> p2 (z>=24)
        {
            dim3 grid(1, BB / 128, 2 * NN);
            gemm_bf<<<grid, 256>>>(yi, OUTF, NN * OUTF, OUTF,
                                   yi, OUTF, NN * OUTF, 0,
                                   fcW, fc2W, (long)OUTF * OUTF,
                                   fcW, 0,
                                   fcb, fc2b, OUTF,
                                   p1, p2, OUTF, NN * OUTF, OUTF, NN);
        }
        // fused tail: mix+tanh, head projections, final
        k_tail<<<BB, 256>>>(p1, p2, G, locW, locb, logzW, logzb, out, t);
    }
}